// round 7
// baseline (speedup 1.0000x reference)
#include <cuda_runtime.h>
#include <cuda_bf16.h>
#include <math.h>
#include <stdint.h>

#define B_  8192
#define D_  768
#define GH_ 384
#define E_  8
#define H_  3072

#define OFF_GATE ((size_t)B_ * D_)
#define OFF_EO   (OFF_GATE + (size_t)B_ * E_)

// ---------------------------------------------------------------------------
// Scratch (device globals)
// ---------------------------------------------------------------------------
__device__ float g_g[(size_t)B_ * GH_];                               // gating hidden
__device__ __align__(16) __nv_bfloat16 g_hhi[(size_t)B_ * D_];        // h bf16 split (gating)
__device__ __align__(16) __nv_bfloat16 g_hlo[(size_t)B_ * D_];
__device__ __align__(16) __nv_bfloat16 g_gw1hi[(size_t)GH_ * D_];
__device__ __align__(16) __nv_bfloat16 g_gw1lo[(size_t)GH_ * D_];
// int8 planes + scales
__device__ __align__(16) int8_t g_hq1[(size_t)B_ * D_];
__device__ __align__(16) int8_t g_hq2[(size_t)B_ * D_];
__device__ float g_hs[B_];
__device__ __align__(16) int8_t g_w1q1[(size_t)E_ * H_ * D_];
__device__ __align__(16) int8_t g_w1q2[(size_t)E_ * H_ * D_];
__device__ float g_w1s[E_ * H_];
__device__ __align__(16) int8_t g_w2q1[(size_t)E_ * D_ * H_];
__device__ __align__(16) int8_t g_w2q2[(size_t)E_ * D_ * H_];
__device__ float g_w2s[E_ * D_];
__device__ __align__(16) float g_hidf[(size_t)E_ * B_ * H_];          // fp32 hid (also transpose scratch)
__device__ __align__(16) int8_t g_aq1[(size_t)E_ * B_ * H_];
__device__ __align__(16) int8_t g_aq2[(size_t)E_ * B_ * H_];
__device__ float g_hidS[E_ * B_];
__device__ float g_tw[B_ * 2];
__device__ int   g_ti[B_ * 2];

// ---------------------------------------------------------------------------
// Helpers
// ---------------------------------------------------------------------------
__device__ __forceinline__ uint32_t smem_to_u32(const void* p) {
    uint32_t a;
    asm("{ .reg .u64 t; cvta.to.shared.u64 t, %1; cvt.u32.u64 %0, t; }" : "=r"(a) : "l"(p));
    return a;
}
__device__ __forceinline__ float geluf(float x) {
    return 0.5f * x * (1.f + erff(x * 0.7071067811865475f));
}
__device__ __forceinline__ void splitbf(float v, __nv_bfloat16& h, __nv_bfloat16& l) {
    h = __float2bfloat16(v);
    l = __float2bfloat16(v - __bfloat162float(h));
}
__device__ __forceinline__ void cpa16(uint32_t dst, const void* src) {
    asm volatile("cp.async.cg.shared.global [%0], [%1], 16;" :: "r"(dst), "l"(src));
}
#define CP_COMMIT() asm volatile("cp.async.commit_group;" ::: "memory")
#define CP_WAIT2()  asm volatile("cp.async.wait_group 2;" ::: "memory")
#define CP_WAIT1()  asm volatile("cp.async.wait_group 1;" ::: "memory")
#define CP_WAIT0()  asm volatile("cp.async.wait_group 0;" ::: "memory")

#define LDSM4(r, addr)                                                          \
    asm volatile("ldmatrix.sync.aligned.m8n8.x4.shared.b16 {%0,%1,%2,%3}, [%4];"\
                 : "=r"((r)[0]), "=r"((r)[1]), "=r"((r)[2]), "=r"((r)[3])       \
                 : "r"(addr))

#define MMA_BF16(d, a, b0, b1)                                                  \
    asm volatile("mma.sync.aligned.m16n8k16.row.col.f32.bf16.bf16.f32 "         \
                 "{%0,%1,%2,%3}, {%4,%5,%6,%7}, {%8,%9}, {%0,%1,%2,%3};"        \
                 : "+f"((d)[0]), "+f"((d)[1]), "+f"((d)[2]), "+f"((d)[3])       \
                 : "r"((a)[0]), "r"((a)[1]), "r"((a)[2]), "r"((a)[3]),          \
                   "r"(b0), "r"(b1))

#define MMA_S8(d, a, b0, b1)                                                    \
    asm volatile("mma.sync.aligned.m16n8k32.row.col.s32.s8.s8.s32 "             \
                 "{%0,%1,%2,%3}, {%4,%5,%6,%7}, {%8,%9}, {%0,%1,%2,%3};"        \
                 : "+r"((d)[0]), "+r"((d)[1]), "+r"((d)[2]), "+r"((d)[3])       \
                 : "r"((a)[0]), "r"((a)[1]), "r"((a)[2]), "r"((a)[3]),          \
                   "r"(b0), "r"(b1))

// ---------------------------------------------------------------------------
// LayerNorm: bf16 hi/lo (gating) + int8 2-plane with per-row scale (experts)
// ---------------------------------------------------------------------------
__global__ void ln_kernel(const float* __restrict__ x,
                          const float* __restrict__ gamma,
                          const float* __restrict__ beta) {
    __shared__ float sv[D_];
    __shared__ float red[64];
    int b = blockIdx.x;
    const float* row = x + (size_t)b * D_;
    float s = 0.f, s2 = 0.f;
    for (int i = threadIdx.x; i < D_; i += blockDim.x) {
        float v = row[i];
        s += v; s2 += v * v;
    }
    for (int o = 16; o; o >>= 1) {
        s  += __shfl_down_sync(0xffffffffu, s,  o);
        s2 += __shfl_down_sync(0xffffffffu, s2, o);
    }
    int wid = threadIdx.x >> 5, lid = threadIdx.x & 31;
    if (lid == 0) { red[wid] = s; red[wid + 32] = s2; }
    __syncthreads();
    int nw = blockDim.x >> 5;
    if (wid == 0) {
        s  = (lid < nw) ? red[lid]      : 0.f;
        s2 = (lid < nw) ? red[lid + 32] : 0.f;
        for (int o = 16; o; o >>= 1) {
            s  += __shfl_down_sync(0xffffffffu, s,  o);
            s2 += __shfl_down_sync(0xffffffffu, s2, o);
        }
        if (lid == 0) { red[0] = s; red[1] = s2; }
    }
    __syncthreads();
    float mu   = red[0] / D_;
    float var  = red[1] / D_ - mu * mu;
    float rstd = rsqrtf(var + 1e-5f);
    float mx = 0.f;
    for (int i = threadIdx.x; i < D_; i += blockDim.x) {
        float v = (row[i] - mu) * rstd * gamma[i] + beta[i];
        sv[i] = v;
        mx = fmaxf(mx, fabsf(v));
        size_t idx = (size_t)b * D_ + i;
        __nv_bfloat16 hi, lo;
        splitbf(v, hi, lo);
        g_hhi[idx] = hi;
        g_hlo[idx] = lo;
    }
    // block max
    for (int o = 16; o; o >>= 1) mx = fmaxf(mx, __shfl_down_sync(0xffffffffu, mx, o));
    if (lid == 0) red[wid] = mx;
    __syncthreads();
    if (wid == 0) {
        mx = (lid < nw) ? red[lid] : 0.f;
        for (int o = 16; o; o >>= 1) mx = fmaxf(mx, __shfl_down_sync(0xffffffffu, mx, o));
        if (lid == 0) red[0] = fmaxf(mx, 1e-30f);
    }
    __syncthreads();
    float sc = red[0];
    if (threadIdx.x == 0) g_hs[b] = sc;
    float inv = 127.f / sc;
    for (int i = threadIdx.x; i < D_; i += blockDim.x) {
        float q = sv[i] * inv;
        float a1 = rintf(q);
        float a2 = rintf((q - a1) * 128.f);
        size_t idx = (size_t)b * D_ + i;
        g_hq1[idx] = (int8_t)(int)a1;
        g_hq2[idx] = (int8_t)(int)a2;
    }
}

// ---------------------------------------------------------------------------
// Plain fp32 transpose: src [E][R][C] -> dst [E][C][R]
// ---------------------------------------------------------------------------
__global__ void transpose_f32_kernel(const float* __restrict__ src,
                                     float* __restrict__ dst, int R, int C) {
    __shared__ float t[32][33];
    int e = blockIdx.z;
    int c0 = blockIdx.x * 32, r0 = blockIdx.y * 32;
    const float* s = src + (size_t)e * R * C;
    #pragma unroll
    for (int i = 0; i < 32; i += 8)
        t[threadIdx.y + i][threadIdx.x] =
            s[(size_t)(r0 + threadIdx.y + i) * C + c0 + threadIdx.x];
    __syncthreads();
    float* d = dst + (size_t)e * C * R;
    #pragma unroll
    for (int i = 0; i < 32; i += 8)
        d[(size_t)(c0 + threadIdx.y + i) * R + r0 + threadIdx.x] =
            t[threadIdx.x][threadIdx.y + i];
}

// bf16 split transpose for gating weights
__global__ void transpose_split_kernel(const float* __restrict__ src,
                                       __nv_bfloat16* __restrict__ dhi,
                                       __nv_bfloat16* __restrict__ dlo,
                                       int R, int C) {
    __shared__ float t[32][33];
    int c0 = blockIdx.x * 32, r0 = blockIdx.y * 32;
    #pragma unroll
    for (int i = 0; i < 32; i += 8)
        t[threadIdx.y + i][threadIdx.x] =
            src[(size_t)(r0 + threadIdx.y + i) * C + c0 + threadIdx.x];
    __syncthreads();
    #pragma unroll
    for (int i = 0; i < 32; i += 8) {
        float v = t[threadIdx.x][threadIdx.y + i];
        __nv_bfloat16 hi, lo;
        splitbf(v, hi, lo);
        size_t o = (size_t)(c0 + threadIdx.y + i) * R + r0 + threadIdx.x;
        dhi[o] = hi;
        dlo[o] = lo;
    }
}

// ---------------------------------------------------------------------------
// Row quantize fp32 [rows][W] -> 2 int8 planes + per-row scale. W <= 3072.
// ---------------------------------------------------------------------------
__global__ void rowquant_kernel(const float* __restrict__ src,
                                int8_t* __restrict__ q1, int8_t* __restrict__ q2,
                                float* __restrict__ scale, int W) {
    __shared__ float sv[3072];
    __shared__ float red[32];
    int row = blockIdx.x;
    const float* s = src + (size_t)row * W;
    float mx = 0.f;
    for (int i = threadIdx.x; i < W; i += blockDim.x) {
        float v = s[i];
        sv[i] = v;
        mx = fmaxf(mx, fabsf(v));
    }
    int wid = threadIdx.x >> 5, lid = threadIdx.x & 31;
    for (int o = 16; o; o >>= 1) mx = fmaxf(mx, __shfl_down_sync(0xffffffffu, mx, o));
    if (lid == 0) red[wid] = mx;
    __syncthreads();
    if (wid == 0) {
        int nw = blockDim.x >> 5;
        mx = (lid < nw) ? red[lid] : 0.f;
        for (int o = 16; o; o >>= 1) mx = fmaxf(mx, __shfl_down_sync(0xffffffffu, mx, o));
        if (lid == 0) red[0] = fmaxf(mx, 1e-30f);
    }
    __syncthreads();
    float sc = red[0];
    if (threadIdx.x == 0) scale[row] = sc;
    float inv = 127.f / sc;
    for (int i = threadIdx.x; i < W; i += blockDim.x) {
        float q = sv[i] * inv;
        float a1 = rintf(q);
        float a2 = rintf((q - a1) * 128.f);
        q1[(size_t)row * W + i] = (int8_t)(int)a1;
        q2[(size_t)row * W + i] = (int8_t)(int)a2;
    }
}

// ---------------------------------------------------------------------------
// int8 2-plane GEMM (Ozaki 3-term): C = op(dequant(A@B^T) + bias)
//   A planes [M,K] int8 (per-row scale sA), B planes [N,K] int8 (per-row=col scale sB).
//   CTA 128x128x64, 8 warps of 64x32 (2Mx4N), 4-stage cp.async, swizzled 64B rows.
//   OUT_MODE: 0 = fp32 +bias, 1 = fp32 gelu(+bias)
// ---------------------------------------------------------------------------
#define QBM 128
#define QBN 128
#define QBK 64
#define QPLANE 8192                    // 128 rows * 64B
#define QSTAGE (4 * QPLANE)            // 32768
#define QNSTG 4
#define SMEM_Q (QNSTG * QSTAGE)        // 131072
#define INV16129 6.2000124e-5f

template <int OUT_MODE>
__global__ void __launch_bounds__(256) gemm_s8(
    const int8_t* __restrict__ Aq1, const int8_t* __restrict__ Aq2,
    const float* __restrict__ sA,
    const int8_t* __restrict__ Bq1, const int8_t* __restrict__ Bq2,
    const float* __restrict__ sB,
    const float* __restrict__ bias, float* __restrict__ OutF,
    int Ktot, size_t aStrideE, size_t sAStrideE,
    size_t bStrideE, size_t sBStrideE, size_t biasStrideE,
    size_t cStrideE, int ldc, int cColStride)
{
    extern __shared__ char smem[];
    uint32_t sbase = smem_to_u32(smem);
    int tid  = threadIdx.x;
    int warp = tid >> 5, lane = tid & 31;
    int e  = blockIdx.z;
    int bm = blockIdx.y * QBM;
    int bn = blockIdx.x * QBN;
    int wm = (warp >> 2) * 64;          // 2 warps along M
    int wn = (warp & 3)  * 32;          // 4 warps along N
    int g  = lane >> 2, tg = lane & 3;
    int mi = lane >> 3, rr = lane & 7;

    const int8_t* pA1 = Aq1 + (size_t)e * aStrideE + (size_t)bm * Ktot;
    const int8_t* pA2 = Aq2 + (size_t)e * aStrideE + (size_t)bm * Ktot;
    const int8_t* pB1 = Bq1 + (size_t)e * bStrideE + (size_t)bn * Ktot;
    const int8_t* pB2 = Bq2 + (size_t)e * bStrideE + (size_t)bn * Ktot;

    // ldmatrix lane bases
    int ahalf = mi >> 1;                               // 16B half within k32
    uint32_t abase[4], aswz[4];
    #pragma unroll
    for (int i = 0; i < 4; i++) {
        int r = wm + i * 16 + (mi & 1) * 8 + rr;
        abase[i] = (uint32_t)r * 64;
        aswz[i]  = (uint32_t)(((r >> 1) & 3) * 16);
    }
    int bhalf = mi & 1;
    uint32_t bbase[2], bswz[2];
    #pragma unroll
    for (int q = 0; q < 2; q++) {
        int r = wn + q * 16 + (mi >> 1) * 8 + rr;
        bbase[q] = (uint32_t)r * 64;
        bswz[q]  = (uint32_t)(((r >> 1) & 3) * 16);
    }

    int acc11[4][4][4], acc12[4][4][4];
    #pragma unroll
    for (int i = 0; i < 4; i++)
        #pragma unroll
        for (int j = 0; j < 4; j++)
            #pragma unroll
            for (int r = 0; r < 4; r++) { acc11[i][j][r] = 0; acc12[i][j][r] = 0; }

    const int NC = Ktot / QBK;

    auto load_chunk = [&](int c, int st) {
        int k0 = c * QBK;
        uint32_t sb = sbase + (uint32_t)st * QSTAGE;
        #pragma unroll
        for (int h = 0; h < 2; h++) {
            int slot = tid + h * 256;
            int row = slot >> 2, col = slot & 3;
            uint32_t d = sb + (uint32_t)row * 64
                       + (uint32_t)((col ^ ((row >> 1) & 3)) * 16);
            size_t ga = (size_t)row * Ktot + k0 + col * 16;
            cpa16(d,                pA1 + ga);
            cpa16(d + QPLANE,       pA2 + ga);
            cpa16(d + 2u * QPLANE,  pB1 + ga);
            cpa16(d + 3u * QPLANE,  pB2 + ga);
        }
        CP_COMMIT();
    };

    load_chunk(0, 0);
    if (NC > 1) load_chunk(1, 1);
    if (NC > 2) load_chunk(2, 2);

    for (int c = 0; c < NC; c++) {
        if (c + 2 < NC)      { CP_WAIT2(); }
        else if (c + 1 < NC) { CP_WAIT1(); }
        else                 { CP_WAIT0(); }
        __syncthreads();
        if (c + 3 < NC) load_chunk(c + 3, (c + 3) % QNSTG);

        uint32_t sb = sbase + (uint32_t)((c % QNSTG) * QSTAGE);
        #pragma unroll
        for (int ks = 0; ks < 2; ks++) {
            uint32_t a1f[4][4], a2f[4][4];
            #pragma unroll
            for (int i = 0; i < 4; i++) {
                uint32_t ad = sb + abase[i]
                            + ((uint32_t)((ks * 2 + ahalf) * 16) ^ aswz[i]);
                LDSM4(a1f[i], ad);
                LDSM4(a2f[i], ad + QPLANE);
            }
            uint32_t b1f[2][4], b2f[2][4];
            #pragma unroll
            for (int q = 0; q < 2; q++) {
                uint32_t bd = sb + 2u * QPLANE + bbase[q]
                            + ((uint32_t)((ks * 2 + bhalf) * 16) ^ bswz[q]);
                LDSM4(b1f[q], bd);
                LDSM4(b2f[q], bd + QPLANE);
            }
            // P11 = a1*b1
            #pragma unroll
            for (int i = 0; i < 4; i++)
                #pragma unroll
                for (int j = 0; j < 4; j++)
                    MMA_S8(acc11[i][j], a1f[i],
                           b1f[j >> 1][(j & 1) * 2], b1f[j >> 1][(j & 1) * 2 + 1]);
            // cross: a1*b2 then a2*b1 (shared acc, 16-issue separation)
            #pragma unroll
            for (int i = 0; i < 4; i++)
                #pragma unroll
                for (int j = 0; j < 4; j++)
                    MMA_S8(acc12[i][j], a1f[i],
                           b2f[j >> 1][(j & 1) * 2], b2f[j >> 1][(j & 1) * 2 + 1]);
            #pragma unroll
            for (int i = 0; i < 4; i++)
                #pragma unroll
                for (int j = 0; j < 4; j++)
                    MMA_S8(acc12[i][j], a2f[i],
                           b1f[j >> 1][(j & 1) * 2], b1f[j >> 1][(j & 1) * 2 + 1]);
        }
    }

    // Epilogue: dequant + bias (+gelu)
    const float* bp  = bias + (size_t)e * biasStrideE;
    const float* sAp = sA + (size_t)e * sAStrideE;
    const float* sBp = sB + (size_t)e * sBStrideE;
    #pragma unroll
    for (int i = 0; i < 4; i++) {
        int r0 = bm + wm + i * 16 + g;
        float sa0 = sAp[r0] * INV16129;
        float sa1 = sAp[r0 + 8] * INV16129;
        #pragma unroll
        for (int j = 0; j < 4; j++) {
            int c0 = bn + wn + j * 8 + tg * 2;
            float sb0 = sBp[c0], sb1 = sBp[c0 + 1];
            float bi0 = bp[c0], bi1 = bp[c0 + 1];
            float p0 = (float)acc11[i][j][0] + (float)acc12[i][j][0] * 0.0078125f;
            float p1 = (float)acc11[i][j][1] + (float)acc12[i][j][1] * 0.0078125f;
            float p2 = (float)acc11[i][j][2] + (float)acc12[i][j][2] * 0.0078125f;
            float p3 = (float)acc11[i][j][3] + (float)acc12[i][j][3] * 0.0078125f;
            float v0 = p0 * (sa0 * sb0) + bi0;
            float v1 = p1 * (sa0 * sb1) + bi1;
            float v2 = p2 * (sa1 * sb0) + bi0;
            float v3 = p3 * (sa1 * sb1) + bi1;
            if (OUT_MODE == 1) { v0 = geluf(v0); v1 = geluf(v1); v2 = geluf(v2); v3 = geluf(v3); }
            size_t rbA = (size_t)e * cStrideE + (size_t)r0 * ldc
                       + (size_t)e * cColStride + c0;
            size_t rbB = rbA + (size_t)8 * ldc;
            OutF[rbA] = v0; OutF[rbA + 1] = v1;
            OutF[rbB] = v2; OutF[rbB + 1] = v3;
        }
    }
}

// ---------------------------------------------------------------------------
// bf16x3 gating GEMM (256x128x32, 8 warps 64x64, 3-stage) — gelu fp32 out
// ---------------------------------------------------------------------------
#define BMT 256
#define BNT 128
#define A_REG 20480
#define B_REG 10240
#define STAGE_B (2 * A_REG + 2 * B_REG)
#define NSTG 3
#define SMEM_TC (NSTG * STAGE_B)

__global__ void __launch_bounds__(256) gemm_gate_bf16(
    const __nv_bfloat16* __restrict__ Ahi, const __nv_bfloat16* __restrict__ Alo,
    const __nv_bfloat16* __restrict__ Bhi, const __nv_bfloat16* __restrict__ Blo,
    const float* __restrict__ bias, float* __restrict__ OutF,
    int Ktot, int ldc)
{
    extern __shared__ char smem[];
    uint32_t sbase = smem_to_u32(smem);
    int tid  = threadIdx.x;
    int warp = tid >> 5, lane = tid & 31;
    int bm = blockIdx.y * BMT;
    int bn = blockIdx.x * BNT;
    int wm = (warp >> 1) * 64;
    int wn = (warp & 1)  * 64;
    int g  = lane >> 2, tg = lane & 3;

    const __nv_bfloat16* pAhi = Ahi + (size_t)bm * Ktot;
    const __nv_bfloat16* pAlo = Alo + (size_t)bm * Ktot;
    const __nv_bfloat16* pBhi = Bhi + (size_t)bn * Ktot;
    const __nv_bfloat16* pBlo = Blo + (size_t)bn * Ktot;

    int mi = lane >> 3, rr = lane & 7;
    uint32_t a_addr = sbase
        + (uint32_t)(wm + (mi & 1) * 8 + rr) * 80 + (uint32_t)(mi >> 1) * 16;
    uint32_t b_addr = sbase + 2u * A_REG
        + (uint32_t)(wn + (mi >> 1) * 8 + rr) * 80 + (uint32_t)(mi & 1) * 16;

    float acc[4][8][4];
    #pragma unroll
    for (int i = 0; i < 4; i++)
        #pragma unroll
        for (int j = 0; j < 8; j++)
            #pragma unroll
            for (int r = 0; r < 4; r++) acc[i][j][r] = 0.f;

    const int NC = Ktot / 32;

    auto load_chunk = [&](int c, int st) {
        int k0 = c * 32;
        uint32_t sb = sbase + (uint32_t)st * STAGE_B;
        #pragma unroll
        for (int i = 0; i < 4; i++) {
            int p = tid + i * 256;
            int row = p >> 2, col = p & 3;
            uint32_t d = sb + (uint32_t)row * 80 + (uint32_t)col * 16;
            size_t go = (size_t)row * Ktot + k0 + col * 8;
            cpa16(d,          pAhi + go);
            cpa16(d + A_REG,  pAlo + go);
        }
        #pragma unroll
        for (int i = 0; i < 2; i++) {
            int p = tid + i * 256;
            int row = p >> 2, col = p & 3;
            uint32_t d = sb + 2u * A_REG + (uint32_t)row * 80 + (uint32_t)col * 16;
            size_t go = (size_t)row * Ktot + k0 + col * 8;
            cpa16(d,          pBhi + go);
            cpa16(d + B_REG,  pBlo + go);
        }
        CP_COMMIT();
    };

    load_chunk(0, 0);
    if (NC > 1) load_chunk(1, 1);

    for (int c = 0; c < NC; c++) {
        if (c + 1 < NC) { CP_WAIT1(); } else { CP_WAIT0(); }
        __syncthreads();
        if (c + 2 < NC) load_chunk(c + 2, (c + 2) % NSTG);

        uint32_t stoff = (uint32_t)((c % NSTG) * STAGE_B);
        #pragma unroll
        for (int ks = 0; ks < 2; ks++) {
            uint32_t ah[4][4], al[4][4];
            #pragma unroll
            for (int i = 0; i < 4; i++) {
                uint32_t ad = a_addr + stoff + (uint32_t)i * 1280 + (uint32_t)ks * 32;
                LDSM4(ah[i], ad);
                LDSM4(al[i], ad + A_REG);
            }
            #pragma unroll
            for (int jh = 0; jh < 2; jh++) {
                uint32_t bh[2][4], bl[2][4];
                #pragma unroll
                for (int jp = 0; jp < 2; jp++) {
                    uint32_t bd = b_addr + stoff
                        + (uint32_t)(jh * 2 + jp) * 1280 + (uint32_t)ks * 32;
                    LDSM4(bh[jp], bd);
                    LDSM4(bl[jp], bd + B_REG);
                }
                #pragma unroll
                for (int i = 0; i < 4; i++)
                    #pragma unroll
                    for (int jl = 0; jl < 4; jl++) {
                        int j = jh * 4 + jl, jp = jl >> 1, hf = (jl & 1) * 2;
                        MMA_BF16(acc[i][j], ah[i], bh[jp][hf], bh[jp][hf + 1]);
                    }
                #pragma unroll
                for (int i = 0; i < 4; i++)
                    #pragma unroll
                    for (int jl = 0; jl < 4; jl++) {
                        int j = jh * 4 + jl, jp = jl >> 1, hf = (jl & 1) * 2;
                        MMA_BF16(acc[i][j], ah[i], bl[jp][hf], bl[jp][hf + 1]);
                    }
                #pragma unroll
                for (int i = 0; i < 4; i++)
                    #pragma unroll
                    for (int jl = 0; jl < 4; jl++) {
                        int j = jh * 4 + jl, jp = jl >> 1, hf = (jl & 1) * 2;
                        MMA_BF16(acc[i][j], al[i], bh[jp][hf], bh[jp][hf + 1]);
                    }
            }
        }
    }

    #pragma unroll
    for (int i = 0; i < 4; i++) {
        int r0 = bm + wm + i * 16 + g;
        #pragma unroll
        for (int j = 0; j < 8; j++) {
            int c0 = bn + wn + j * 8 + tg * 2;
            float bi0 = bias[c0], bi1 = bias[c0 + 1];
            size_t rbA = (size_t)r0 * ldc + c0;
            size_t rbB = rbA + (size_t)8 * ldc;
            OutF[rbA]     = geluf(acc[i][j][0] + bi0);
            OutF[rbA + 1] = geluf(acc[i][j][1] + bi1);
            OutF[rbB]     = geluf(acc[i][j][2] + bi0);
            OutF[rbB + 1] = geluf(acc[i][j][3] + bi1);
        }
    }
}

// ---------------------------------------------------------------------------
__global__ void gate_kernel(const float* __restrict__ gw2,
                            const float* __restrict__ gb2,
                            float* __restrict__ dout) {
    int b = blockIdx.x * (blockDim.x >> 5) + (threadIdx.x >> 5);
    if (b >= B_) return;
    int lane = threadIdx.x & 31;
    int e = lane & 7, s = lane >> 3;

    const float* gr = g_g + (size_t)b * GH_;
    float acc = 0.f;
    int k0 = s * (GH_ / 4);
    #pragma unroll 4
    for (int k = k0; k < k0 + GH_ / 4; k++)
        acc = fmaf(gr[k], gw2[k * E_ + e], acc);
    acc += __shfl_xor_sync(0xffffffffu, acc, 8);
    acc += __shfl_xor_sync(0xffffffffu, acc, 16);
    float logit = acc + gb2[e];

    float m = logit;
    for (int o = 4; o; o >>= 1) m = fmaxf(m, __shfl_xor_sync(0xffffffffu, m, o));
    float p = (lane < E_) ? expf(logit - m) : 0.f;
    float ssum = p;
    for (int o = 16; o; o >>= 1) ssum += __shfl_xor_sync(0xffffffffu, ssum, o);
    float prob = p / ssum;
    if (lane < E_) dout[OFF_GATE + (size_t)b * E_ + lane] = prob;

    float v1 = (lane < E_) ? prob : -1.f; int i1 = lane;
    for (int o = 16; o; o >>= 1) {
        float ov = __shfl_xor_sync(0xffffffffu, v1, o);
        int   oi = __shfl_xor_sync(0xffffffffu, i1, o);
        if (ov > v1 || (ov == v1 && oi < i1)) { v1 = ov; i1 = oi; }
    }
    float v2 = (lane < E_ && lane != i1) ? prob : -1.f; int i2 = lane;
    for (int o = 16; o; o >>= 1) {
        float ov = __shfl_xor_sync(0xffffffffu, v2, o);
        int   oi = __shfl_xor_sync(0xffffffffu, i2, o);
        if (ov > v2 || (ov == v2 && oi < i2)) { v2 = ov; i2 = oi; }
    }
    if (lane == 0) {
        float sw = v1 + v2;
        g_tw[b * 2 + 0] = v1 / sw;
        g_tw[b * 2 + 1] = v2 / sw;
        g_ti[b * 2 + 0] = i1;
        g_ti[b * 2 + 1] = i2;
    }
}

// ---------------------------------------------------------------------------
__global__ void combine_kernel(float* __restrict__ dout) {
    size_t i = (size_t)blockIdx.x * blockDim.x + threadIdx.x;
    if (i >= (size_t)B_ * D_) return;
    int b = (int)(i / D_), d = (int)(i % D_);
    int   i0 = g_ti[b * 2], i1 = g_ti[b * 2 + 1];
    float w0 = g_tw[b * 2], w1 = g_tw[b * 2 + 1];
    const float* eo = dout + OFF_EO + (size_t)b * E_ * D_;
    dout[i] = w0 * eo[(size_t)i0 * D_ + d] + w1 * eo[(size_t)i1 * D_ + d];
}

// ---------------------------------------------------------------------------
extern "C" void kernel_launch(void* const* d_in, const int* in_sizes, int n_in,
                              void* d_out, int out_size) {
    const float* x     = (const float*)d_in[0];
    const float* gamma = (const float*)d_in[1];
    const float* beta  = (const float*)d_in[2];
    const float* gw1   = (const float*)d_in[3];
    const float* gb1   = (const float*)d_in[4];
    const float* gw2   = (const float*)d_in[5];
    const float* gb2   = (const float*)d_in[6];
    const float* ew1   = (const float*)d_in[7];
    const float* eb1   = (const float*)d_in[8];
    const float* ew2   = (const float*)d_in[9];
    const float* eb2   = (const float*)d_in[10];
    float* out = (float*)d_out;

    float *pg, *phs, *pw1s, *pw2s, *phidf, *phidS;
    __nv_bfloat16 *phhi, *phlo, *pgw1hi, *pgw1lo;
    int8_t *phq1, *phq2, *pw1q1, *pw1q2, *pw2q1, *pw2q2, *paq1, *paq2;
    cudaGetSymbolAddress((void**)&pg,     g_g);
    cudaGetSymbolAddress((void**)&phhi,   g_hhi);
    cudaGetSymbolAddress((void**)&phlo,   g_hlo);
    cudaGetSymbolAddress((void**)&pgw1hi, g_gw1hi);
    cudaGetSymbolAddress((void**)&pgw1lo, g_gw1lo);
    cudaGetSymbolAddress((void**)&phq1,   g_hq1);
    cudaGetSymbolAddress((void**)&phq2,   g_hq2);
    cudaGetSymbolAddress((void**)&phs,    g_hs);
    cudaGetSymbolAddress((void**)&pw1q1,  g_w1q1);
    cudaGetSymbolAddress((void**)&pw1q2,  g_w1q2);
    cudaGetSymbolAddress((void**)&pw1s,   g_w1s);
    cudaGetSymbolAddress((void**)&pw2q1,  g_w2q1);
    cudaGetSymbolAddress((void**)&pw2q2,  g_w2q2);
    cudaGetSymbolAddress((void**)&pw2s,   g_w2s);
    cudaGetSymbolAddress((void**)&phidf,  g_hidf);
    cudaGetSymbolAddress((void**)&paq1,   g_aq1);
    cudaGetSymbolAddress((void**)&paq2,   g_aq2);
    cudaGetSymbolAddress((void**)&phidS,  g_hidS);

    cudaFuncSetAttribute(gemm_s8<0>, cudaFuncAttributeMaxDynamicSharedMemorySize, SMEM_Q);
    cudaFuncSetAttribute(gemm_s8<1>, cudaFuncAttributeMaxDynamicSharedMemorySize, SMEM_Q);
    cudaFuncSetAttribute(gemm_gate_bf16, cudaFuncAttributeMaxDynamicSharedMemorySize, SMEM_TC);

    // 1. LayerNorm: bf16 split (gating) + int8 planes (experts)
    ln_kernel<<<B_, 256>>>(x, gamma, beta);

    // 2. ew1 -> transpose fp32 scratch -> row-quant ([E][H][D], scale per (e,n))
    transpose_f32_kernel<<<dim3(H_ / 32, D_ / 32, E_), dim3(32, 8)>>>(ew1, phidf, D_, H_);
    rowquant_kernel<<<E_ * H_, 256>>>(phidf, pw1q1, pw1q2, pw1s, D_);

    // 3. ew2 -> transpose -> row-quant ([E][D][H])
    transpose_f32_kernel<<<dim3(D_ / 32, H_ / 32, E_), dim3(32, 8)>>>(ew2, phidf, H_, D_);
    rowquant_kernel<<<E_ * D_, 256>>>(phidf, pw2q1, pw2q2, pw2s, H_);

    // 4. gating weight transpose (bf16 split)
    transpose_split_kernel<<<dim3(GH_ / 32, D_ / 32, 1), dim3(32, 8)>>>(gw1, pgw1hi, pgw1lo, D_, GH_);

    // 5. Gating GEMM (bf16x3, exact path) + softmax/top-2
    gemm_gate_bf16<<<dim3(GH_ / BNT, B_ / BMT, 1), 256, SMEM_TC>>>(
        phhi, phlo, pgw1hi, pgw1lo, gb1, pg, D_, GH_);
    gate_kernel<<<(B_ + 7) / 8, 256>>>(gw2, gb2, out);

    // 6. Expert GEMM1 (int8): hid = gelu(h @ ew1 + eb1), fp32 out
    gemm_s8<1><<<dim3(H_ / QBN, B_ / QBM, E_), 256, SMEM_Q>>>(
        phq1, phq2, phs, pw1q1, pw1q2, pw1s, eb1, phidf,
        D_, 0, 0, (size_t)H_ * D_, H_, H_,
        (size_t)B_ * H_, H_, 0);

    // 7. Quantize hid rows (per (e,b), W=H)
    rowquant_kernel<<<E_ * B_, 256>>>(phidf, paq1, paq2, phidS, H_);

    // 8. Expert GEMM2 (int8): expert_outputs = hid @ ew2 + eb2 (fp32 interleaved)
    gemm_s8<0><<<dim3(D_ / QBN, B_ / QBM, E_), 256, SMEM_Q>>>(
        paq1, paq2, phidS, pw2q1, pw2q2, pw2s, eb2, out + OFF_EO,
        H_, (size_t)B_ * H_, B_, (size_t)D_ * H_, D_, D_,
        0, E_ * D_, D_);

    // 9. Combine -> result
    combine_kernel<<<((int)((size_t)B_ * D_ + 255) / 256), 256>>>(out);
}

// round 8
// speedup vs baseline: 2.6202x; 2.6202x over previous
#include <cuda_runtime.h>
#include <cuda_bf16.h>
#include <math.h>
#include <stdint.h>

#define B_  8192
#define D_  768
#define GH_ 384
#define E_  8
#define H_  3072

#define OFF_GATE ((size_t)B_ * D_)
#define OFF_EO   (OFF_GATE + (size_t)B_ * E_)

__device__ float g_g[(size_t)B_ * GH_];
__device__ __align__(16) __nv_bfloat16 g_hhi[(size_t)B_ * D_];
__device__ __align__(16) __nv_bfloat16 g_hlo[(size_t)B_ * D_];
__device__ __align__(16) __nv_bfloat16 g_gw1hi[(size_t)GH_ * D_];
__device__ __align__(16) __nv_bfloat16 g_gw1lo[(size_t)GH_ * D_];
__device__ __align__(16) __nv_bfloat16 g_w1hi[(size_t)E_ * H_ * D_];
__device__ __align__(16) __nv_bfloat16 g_w1lo[(size_t)E_ * H_ * D_];
__device__ __align__(16) __nv_bfloat16 g_w2hi[(size_t)E_ * D_ * H_];
__device__ __align__(16) __nv_bfloat16 g_w2lo[(size_t)E_ * D_ * H_];
__device__ __align__(16) __nv_bfloat16 g_hidhi[(size_t)E_ * B_ * H_];
__device__ __align__(16) __nv_bfloat16 g_hidlo[(size_t)E_ * B_ * H_];
__device__ float g_tw[B_ * 2];
__device__ int   g_ti[B_ * 2];

__device__ __forceinline__ uint32_t smem_to_u32(const void* p) {
    uint32_t a;
    asm("{ .reg .u64 t; cvta.to.shared.u64 t, %1; cvt.u32.u64 %0, t; }" : "=r"(a) : "l"(p));
    return a;
}
__device__ __forceinline__ float geluf(float x) {
    return 0.5f * x * (1.f + erff(x * 0.7071067811865475f));
}
__device__ __forceinline__ void splitbf(float v, __nv_bfloat16& h, __nv_bfloat16& l) {
    h = __float2bfloat16(v);
    l = __float2bfloat16(v - __bfloat162float(h));
}
__device__ __forceinline__ uint32_t pack2(__nv_bfloat16 a, __nv_bfloat16 b) {
    return (uint32_t)__bfloat16_as_ushort(a) | ((uint32_t)__bfloat16_as_ushort(b) << 16);
}
__device__ __forceinline__ void cpa16(uint32_t dst, const void* src) {
    asm volatile("cp.async.cg.shared.global [%0], [%1], 16;" :: "r"(dst), "l"(src));
}
#define CP_COMMIT() asm volatile("cp.async.commit_group;" ::: "memory")
#define CP_WAIT1()  asm volatile("cp.async.wait_group 1;" ::: "memory")
#define CP_WAIT0()  asm volatile("cp.async.wait_group 0;" ::: "memory")

#define LDSM4(r, addr)                                                          \
    asm volatile("ldmatrix.sync.aligned.m8n8.x4.shared.b16 {%0,%1,%2,%3}, [%4];"\
                 : "=r"((r)[0]), "=r"((r)[1]), "=r"((r)[2]), "=r"((r)[3])       \
                 : "r"(addr))

#define MMA_BF16(d, a, b0, b1)                                                  \
    asm volatile("mma.sync.aligned.m16n8k16.row.col.f32.bf16.bf16.f32 "         \
                 "{%0,%1,%2,%3}, {%4,%5,%6,%7}, {%8,%9}, {%0,%1,%2,%3};"        \
                 : "+f"((d)[0]), "+f"((d)[1]), "+f"((d)[2]), "+f"((d)[3])       \
                 : "r"((a)[0]), "r"((a)[1]), "r"((a)[2]), "r"((a)[3]),          \
                   "r"(b0), "r"(b1))

// ---------------------------------------------------------------------------
__global__ void ln_kernel(const float* __restrict__ x,
                          const float* __restrict__ gamma,
                          const float* __restrict__ beta) {
    int b = blockIdx.x;
    const float* row = x + (size_t)b * D_;
    float s = 0.f, s2 = 0.f;
    for (int i = threadIdx.x; i < D_; i += blockDim.x) {
        float v = row[i];
        s += v; s2 += v * v;
    }
    __shared__ float red[64];
    for (int o = 16; o; o >>= 1) {
        s  += __shfl_down_sync(0xffffffffu, s,  o);
        s2 += __shfl_down_sync(0xffffffffu, s2, o);
    }
    int wid = threadIdx.x >> 5, lid = threadIdx.x & 31;
    if (lid == 0) { red[wid] = s; red[wid + 32] = s2; }
    __syncthreads();
    int nw = blockDim.x >> 5;
    if (wid == 0) {
        s  = (lid < nw) ? red[lid]      : 0.f;
        s2 = (lid < nw) ? red[lid + 32] : 0.f;
        for (int o = 16; o; o >>= 1) {
            s  += __shfl_down_sync(0xffffffffu, s,  o);
            s2 += __shfl_down_sync(0xffffffffu, s2, o);
        }
        if (lid == 0) { red[0] = s; red[1] = s2; }
    }
    __syncthreads();
    float mu   = red[0] / D_;
    float var  = red[1] / D_ - mu * mu;
    float rstd = rsqrtf(var + 1e-5f);
    for (int i = threadIdx.x; i < D_; i += blockDim.x) {
        float v = (row[i] - mu) * rstd * gamma[i] + beta[i];
        size_t idx = (size_t)b * D_ + i;
        __nv_bfloat16 hi, lo;
        splitbf(v, hi, lo);
        g_hhi[idx] = hi;
        g_hlo[idx] = lo;
    }
}

// ---------------------------------------------------------------------------
__global__ void transpose_split_kernel(const float* __restrict__ src,
                                       __nv_bfloat16* __restrict__ dhi,
                                       __nv_bfloat16* __restrict__ dlo,
                                       int R, int C) {
    __shared__ float t[32][33];
    int e = blockIdx.z;
    int c0 = blockIdx.x * 32, r0 = blockIdx.y * 32;
    const float* s = src + (size_t)e * R * C;
    #pragma unroll
    for (int i = 0; i < 32; i += 8)
        t[threadIdx.y + i][threadIdx.x] =
            s[(size_t)(r0 + threadIdx.y + i) * C + c0 + threadIdx.x];
    __syncthreads();
    size_t ob = (size_t)e * C * R;
    #pragma unroll
    for (int i = 0; i < 32; i += 8) {
        float v = t[threadIdx.x][threadIdx.y + i];
        __nv_bfloat16 hi, lo;
        splitbf(v, hi, lo);
        size_t o = ob + (size_t)(c0 + threadIdx.y + i) * R + r0 + threadIdx.x;
        dhi[o] = hi;
        dlo[o] = lo;
    }
}

// ---------------------------------------------------------------------------
// bf16x3 GEMM: 128x128x32 CTA tile, 4 warps of 64x64 (2x2), 2-stage pipeline,
// 2 CTAs/SM so one CTA's barrier/wait stalls are hidden by the other.
// OUT_MODE: 0 = fp32 +bias, 1 = fp32 gelu, 2 = gelu + bf16 hi/lo split
// ---------------------------------------------------------------------------
#define A_REG 10240                     // 128 rows * 80B pitch
#define B_REG 10240
#define STAGE_B (2 * A_REG + 2 * B_REG) // 40960
#define NSTG 2
#define SMEM_TC (NSTG * STAGE_B)        // 81920

template <int OUT_MODE>
__global__ void __launch_bounds__(128, 2) gemm_bf16x3(
    const __nv_bfloat16* __restrict__ Ahi, const __nv_bfloat16* __restrict__ Alo,
    const __nv_bfloat16* __restrict__ Bhi, const __nv_bfloat16* __restrict__ Blo,
    const float* __restrict__ bias,
    __nv_bfloat16* __restrict__ OutHi, __nv_bfloat16* __restrict__ OutLo,
    float* __restrict__ OutF,
    int Ktot, size_t aStrideE, size_t bStrideE, size_t biasStrideE,
    size_t cStrideE, int ldc, int cColStride)
{
    extern __shared__ char smem[];
    uint32_t sbase = smem_to_u32(smem);
    int tid  = threadIdx.x;
    int warp = tid >> 5, lane = tid & 31;
    int e  = blockIdx.z;
    int bm = blockIdx.y * 128;
    int bn = blockIdx.x * 128;
    int wm = (warp >> 1) * 64;          // 2 warps along M
    int wn = (warp & 1)  * 64;          // 2 warps along N
    int g  = lane >> 2, tg = lane & 3;

    const __nv_bfloat16* pAhi = Ahi + (size_t)e * aStrideE + (size_t)bm * Ktot;
    const __nv_bfloat16* pAlo = Alo + (size_t)e * aStrideE + (size_t)bm * Ktot;
    const __nv_bfloat16* pBhi = Bhi + (size_t)e * bStrideE + (size_t)bn * Ktot;
    const __nv_bfloat16* pBlo = Blo + (size_t)e * bStrideE + (size_t)bn * Ktot;

    int mi = lane >> 3, rr = lane & 7;
    uint32_t a_addr = sbase
        + (uint32_t)(wm + (mi & 1) * 8 + rr) * 80 + (uint32_t)(mi >> 1) * 16;
    uint32_t b_addr = sbase + 2u * A_REG
        + (uint32_t)(wn + (mi >> 1) * 8 + rr) * 80 + (uint32_t)(mi & 1) * 16;

    float acc[4][8][4];
    #pragma unroll
    for (int i = 0; i < 4; i++)
        #pragma unroll
        for (int j = 0; j < 8; j++)
            #pragma unroll
            for (int r = 0; r < 4; r++) acc[i][j][r] = 0.f;

    const int NC = Ktot / 32;

    auto load_chunk = [&](int c, int st) {
        int k0 = c * 32;
        uint32_t sb = sbase + (uint32_t)st * STAGE_B;
        #pragma unroll
        for (int i = 0; i < 4; i++) {           // A: 512 16B units/plane
            int p = tid + i * 128;
            int row = p >> 2, col = p & 3;
            uint32_t d = sb + (uint32_t)row * 80 + (uint32_t)col * 16;
            size_t go = (size_t)row * Ktot + k0 + col * 8;
            cpa16(d,          pAhi + go);
            cpa16(d + A_REG,  pAlo + go);
        }
        #pragma unroll
        for (int i = 0; i < 4; i++) {           // B: 512 16B units/plane
            int p = tid + i * 128;
            int row = p >> 2, col = p & 3;
            uint32_t d = sb + 2u * A_REG + (uint32_t)row * 80 + (uint32_t)col * 16;
            size_t go = (size_t)row * Ktot + k0 + col * 8;
            cpa16(d,          pBhi + go);
            cpa16(d + B_REG,  pBlo + go);
        }
        CP_COMMIT();
    };

    load_chunk(0, 0);
    if (NC > 1) load_chunk(1, 1);

    for (int c = 0; c < NC; c++) {
        if (c + 1 < NC) { CP_WAIT1(); } else { CP_WAIT0(); }
        __syncthreads();

        uint32_t stoff = (uint32_t)((c % NSTG) * STAGE_B);
        #pragma unroll
        for (int ks = 0; ks < 2; ks++) {
            uint32_t ah[4][4], al[4][4];
            #pragma unroll
            for (int i = 0; i < 4; i++) {
                uint32_t ad = a_addr + stoff + (uint32_t)i * 1280 + (uint32_t)ks * 32;
                LDSM4(ah[i], ad);
                LDSM4(al[i], ad + A_REG);
            }
            #pragma unroll
            for (int jh = 0; jh < 2; jh++) {
                uint32_t bh[2][4], bl[2][4];
                #pragma unroll
                for (int jp = 0; jp < 2; jp++) {
                    uint32_t bd = b_addr + stoff
                        + (uint32_t)(jh * 2 + jp) * 1280 + (uint32_t)ks * 32;
                    LDSM4(bh[jp], bd);
                    LDSM4(bl[jp], bd + B_REG);
                }
                #pragma unroll
                for (int i = 0; i < 4; i++)
                    #pragma unroll
                    for (int jl = 0; jl < 4; jl++) {
                        int j = jh * 4 + jl, jp = jl >> 1, hf = (jl & 1) * 2;
                        MMA_BF16(acc[i][j], ah[i], bh[jp][hf], bh[jp][hf + 1]);
                    }
                #pragma unroll
                for (int i = 0; i < 4; i++)
                    #pragma unroll
                    for (int jl = 0; jl < 4; jl++) {
                        int j = jh * 4 + jl, jp = jl >> 1, hf = (jl & 1) * 2;
                        MMA_BF16(acc[i][j], ah[i], bl[jp][hf], bl[jp][hf + 1]);
                    }
                #pragma unroll
                for (int i = 0; i < 4; i++)
                    #pragma unroll
                    for (int jl = 0; jl < 4; jl++) {
                        int j = jh * 4 + jl, jp = jl >> 1, hf = (jl & 1) * 2;
                        MMA_BF16(acc[i][j], al[i], bh[jp][hf], bh[jp][hf + 1]);
                    }
            }
        }
        __syncthreads();                         // stage c%2 fully consumed
        if (c + 2 < NC) load_chunk(c + 2, c % NSTG);
    }

    const float* bp = bias + (size_t)e * biasStrideE;
    #pragma unroll
    for (int i = 0; i < 4; i++) {
        int r0 = bm + wm + i * 16 + g;
        #pragma unroll
        for (int j = 0; j < 8; j++) {
            int c0 = bn + wn + j * 8 + tg * 2;
            float bi0 = bp[c0], bi1 = bp[c0 + 1];
            float v0 = acc[i][j][0] + bi0, v1 = acc[i][j][1] + bi1;
            float v2 = acc[i][j][2] + bi0, v3 = acc[i][j][3] + bi1;
            size_t rbA = (size_t)e * cStrideE + (size_t)r0 * ldc
                       + (size_t)e * cColStride + c0;
            size_t rbB = rbA + (size_t)8 * ldc;
            if (OUT_MODE == 0) {
                OutF[rbA] = v0; OutF[rbA + 1] = v1;
                OutF[rbB] = v2; OutF[rbB + 1] = v3;
            } else if (OUT_MODE == 1) {
                OutF[rbA] = geluf(v0); OutF[rbA + 1] = geluf(v1);
                OutF[rbB] = geluf(v2); OutF[rbB + 1] = geluf(v3);
            } else {
                v0 = geluf(v0); v1 = geluf(v1); v2 = geluf(v2); v3 = geluf(v3);
                __nv_bfloat16 h0, l0, h1, l1;
                splitbf(v0, h0, l0); splitbf(v1, h1, l1);
                *(uint32_t*)(OutHi + rbA) = pack2(h0, h1);
                *(uint32_t*)(OutLo + rbA) = pack2(l0, l1);
                splitbf(v2, h0, l0); splitbf(v3, h1, l1);
                *(uint32_t*)(OutHi + rbB) = pack2(h0, h1);
                *(uint32_t*)(OutLo + rbB) = pack2(l0, l1);
            }
        }
    }
}

// ---------------------------------------------------------------------------
__global__ void gate_kernel(const float* __restrict__ gw2,
                            const float* __restrict__ gb2,
                            float* __restrict__ dout) {
    int b = blockIdx.x * (blockDim.x >> 5) + (threadIdx.x >> 5);
    if (b >= B_) return;
    int lane = threadIdx.x & 31;
    int e = lane & 7, s = lane >> 3;

    const float* gr = g_g + (size_t)b * GH_;
    float acc = 0.f;
    int k0 = s * (GH_ / 4);
    #pragma unroll 4
    for (int k = k0; k < k0 + GH_ / 4; k++)
        acc = fmaf(gr[k], gw2[k * E_ + e], acc);
    acc += __shfl_xor_sync(0xffffffffu, acc, 8);
    acc += __shfl_xor_sync(0xffffffffu, acc, 16);
    float logit = acc + gb2[e];

    float m = logit;
    for (int o = 4; o; o >>= 1) m = fmaxf(m, __shfl_xor_sync(0xffffffffu, m, o));
    float p = (lane < E_) ? expf(logit - m) : 0.f;
    float ssum = p;
    for (int o = 16; o; o >>= 1) ssum += __shfl_xor_sync(0xffffffffu, ssum, o);
    float prob = p / ssum;
    if (lane < E_) dout[OFF_GATE + (size_t)b * E_ + lane] = prob;

    float v1 = (lane < E_) ? prob : -1.f; int i1 = lane;
    for (int o = 16; o; o >>= 1) {
        float ov = __shfl_xor_sync(0xffffffffu, v1, o);
        int   oi = __shfl_xor_sync(0xffffffffu, i1, o);
        if (ov > v1 || (ov == v1 && oi < i1)) { v1 = ov; i1 = oi; }
    }
    float v2 = (lane < E_ && lane != i1) ? prob : -1.f; int i2 = lane;
    for (int o = 16; o; o >>= 1) {
        float ov = __shfl_xor_sync(0xffffffffu, v2, o);
        int   oi = __shfl_xor_sync(0xffffffffu, i2, o);
        if (ov > v2 || (ov == v2 && oi < i2)) { v2 = ov; i2 = oi; }
    }
    if (lane == 0) {
        float sw = v1 + v2;
        g_tw[b * 2 + 0] = v1 / sw;
        g_tw[b * 2 + 1] = v2 / sw;
        g_ti[b * 2 + 0] = i1;
        g_ti[b * 2 + 1] = i2;
    }
}

// ---------------------------------------------------------------------------
__global__ void combine_kernel(float* __restrict__ dout) {
    size_t i = (size_t)blockIdx.x * blockDim.x + threadIdx.x;
    if (i >= (size_t)B_ * D_) return;
    int b = (int)(i / D_), d = (int)(i % D_);
    int   i0 = g_ti[b * 2], i1 = g_ti[b * 2 + 1];
    float w0 = g_tw[b * 2], w1 = g_tw[b * 2 + 1];
    const float* eo = dout + OFF_EO + (size_t)b * E_ * D_;
    dout[i] = w0 * eo[(size_t)i0 * D_ + d] + w1 * eo[(size_t)i1 * D_ + d];
}

// ---------------------------------------------------------------------------
extern "C" void kernel_launch(void* const* d_in, const int* in_sizes, int n_in,
                              void* d_out, int out_size) {
    const float* x     = (const float*)d_in[0];
    const float* gamma = (const float*)d_in[1];
    const float* beta  = (const float*)d_in[2];
    const float* gw1   = (const float*)d_in[3];
    const float* gb1   = (const float*)d_in[4];
    const float* gw2   = (const float*)d_in[5];
    const float* gb2   = (const float*)d_in[6];
    const float* ew1   = (const float*)d_in[7];
    const float* eb1   = (const float*)d_in[8];
    const float* ew2   = (const float*)d_in[9];
    const float* eb2   = (const float*)d_in[10];
    float* out = (float*)d_out;

    float *pg;
    __nv_bfloat16 *phhi, *phlo, *pgw1hi, *pgw1lo, *pw1hi, *pw1lo, *pw2hi, *pw2lo,
                  *phidhi, *phidlo;
    cudaGetSymbolAddress((void**)&pg,     g_g);
    cudaGetSymbolAddress((void**)&phhi,   g_hhi);
    cudaGetSymbolAddress((void**)&phlo,   g_hlo);
    cudaGetSymbolAddress((void**)&pgw1hi, g_gw1hi);
    cudaGetSymbolAddress((void**)&pgw1lo, g_gw1lo);
    cudaGetSymbolAddress((void**)&pw1hi,  g_w1hi);
    cudaGetSymbolAddress((void**)&pw1lo,  g_w1lo);
    cudaGetSymbolAddress((void**)&pw2hi,  g_w2hi);
    cudaGetSymbolAddress((void**)&pw2lo,  g_w2lo);
    cudaGetSymbolAddress((void**)&phidhi, g_hidhi);
    cudaGetSymbolAddress((void**)&phidlo, g_hidlo);

    cudaFuncSetAttribute(gemm_bf16x3<0>, cudaFuncAttributeMaxDynamicSharedMemorySize, SMEM_TC);
    cudaFuncSetAttribute(gemm_bf16x3<1>, cudaFuncAttributeMaxDynamicSharedMemorySize, SMEM_TC);
    cudaFuncSetAttribute(gemm_bf16x3<2>, cudaFuncAttributeMaxDynamicSharedMemorySize, SMEM_TC);

    // 1. LayerNorm + bf16 split
    ln_kernel<<<B_, 256>>>(x, gamma, beta);

    // 2-4. Weight transposes + splits (K-major [N,K] operands)
    transpose_split_kernel<<<dim3(H_ / 32, D_ / 32, E_), dim3(32, 8)>>>(ew1, pw1hi, pw1lo, D_, H_);
    transpose_split_kernel<<<dim3(D_ / 32, H_ / 32, E_), dim3(32, 8)>>>(ew2, pw2hi, pw2lo, H_, D_);
    transpose_split_kernel<<<dim3(GH_ / 32, D_ / 32, 1), dim3(32, 8)>>>(gw1, pgw1hi, pgw1lo, D_, GH_);

    // 5. Expert GEMM1: hid[e] = gelu(h @ ew1[e] + eb1[e]), bf16 split out
    gemm_bf16x3<2><<<dim3(H_ / 128, B_ / 128, E_), 128, SMEM_TC>>>(
        phhi, phlo, pw1hi, pw1lo, eb1,
        phidhi, phidlo, nullptr,
        D_, 0, (size_t)H_ * D_, H_,
        (size_t)B_ * H_, H_, 0);

    // 6. Expert GEMM2: expert_outputs[:,e,:] = hid[e] @ ew2[e] + eb2[e] (fp32)
    gemm_bf16x3<0><<<dim3(D_ / 128, B_ / 128, E_), 128, SMEM_TC>>>(
        phidhi, phidlo, pw2hi, pw2lo, eb2,
        nullptr, nullptr, out + OFF_EO,
        H_, (size_t)B_ * H_, (size_t)D_ * H_, D_,
        0, E_ * D_, D_);

    // 7. Gating layer1: g = gelu(h @ gw1 + gb1), fp32
    gemm_bf16x3<1><<<dim3(GH_ / 128, B_ / 128, 1), 128, SMEM_TC>>>(
        phhi, phlo, pgw1hi, pgw1lo, gb1,
        nullptr, nullptr, pg,
        D_, 0, 0, 0, 0, GH_, 0);

    // 8. Gate softmax + top-2
    gate_kernel<<<(B_ + 7) / 8, 256>>>(gw2, gb2, out);

    // 9. Combine -> result
    combine_kernel<<<((int)((size_t)B_ * D_ + 255) / 256), 256>>>(out);
}

// round 9
// speedup vs baseline: 3.0348x; 1.1582x over previous
#include <cuda_runtime.h>
#include <cuda_bf16.h>
#include <math.h>
#include <stdint.h>

#define B_  8192
#define D_  768
#define GH_ 384
#define E_  8
#define H_  3072

#define OFF_GATE ((size_t)B_ * D_)
#define OFF_EO   (OFF_GATE + (size_t)B_ * E_)

__device__ float g_g[(size_t)B_ * GH_];
__device__ __align__(16) __nv_bfloat16 g_hhi[(size_t)B_ * D_];
__device__ __align__(16) __nv_bfloat16 g_hlo[(size_t)B_ * D_];
__device__ __align__(16) __nv_bfloat16 g_gw1hi[(size_t)GH_ * D_];
__device__ __align__(16) __nv_bfloat16 g_gw1lo[(size_t)GH_ * D_];
__device__ __align__(16) __nv_bfloat16 g_w1hi[(size_t)E_ * H_ * D_];
__device__ __align__(16) __nv_bfloat16 g_w1lo[(size_t)E_ * H_ * D_];
__device__ __align__(16) __nv_bfloat16 g_w2hi[(size_t)E_ * D_ * H_];
__device__ __align__(16) __nv_bfloat16 g_w2lo[(size_t)E_ * D_ * H_];
__device__ __align__(16) __nv_bfloat16 g_hidhi[(size_t)E_ * B_ * H_];
__device__ __align__(16) __nv_bfloat16 g_hidlo[(size_t)E_ * B_ * H_];
__device__ float g_tw[B_ * 2];
__device__ int   g_ti[B_ * 2];

__device__ __forceinline__ uint32_t smem_to_u32(const void* p) {
    uint32_t a;
    asm("{ .reg .u64 t; cvta.to.shared.u64 t, %1; cvt.u32.u64 %0, t; }" : "=r"(a) : "l"(p));
    return a;
}
__device__ __forceinline__ float geluf(float x) {
    return 0.5f * x * (1.f + erff(x * 0.7071067811865475f));
}
__device__ __forceinline__ void splitbf(float v, __nv_bfloat16& h, __nv_bfloat16& l) {
    h = __float2bfloat16(v);
    l = __float2bfloat16(v - __bfloat162float(h));
}
__device__ __forceinline__ uint32_t pack2(__nv_bfloat16 a, __nv_bfloat16 b) {
    return (uint32_t)__bfloat16_as_ushort(a) | ((uint32_t)__bfloat16_as_ushort(b) << 16);
}
__device__ __forceinline__ void cpa16(uint32_t dst, const void* src) {
    asm volatile("cp.async.cg.shared.global [%0], [%1], 16;" :: "r"(dst), "l"(src));
}
#define CP_COMMIT() asm volatile("cp.async.commit_group;" ::: "memory")
#define CP_WAIT1()  asm volatile("cp.async.wait_group 1;" ::: "memory")
#define CP_WAIT0()  asm volatile("cp.async.wait_group 0;" ::: "memory")

#define LDSM4(r, addr)                                                          \
    asm volatile("ldmatrix.sync.aligned.m8n8.x4.shared.b16 {%0,%1,%2,%3}, [%4];"\
                 : "=r"((r)[0]), "=r"((r)[1]), "=r"((r)[2]), "=r"((r)[3])       \
                 : "r"(addr))

#define MMA_BF16(d, a, b0, b1)                                                  \
    asm volatile("mma.sync.aligned.m16n8k16.row.col.f32.bf16.bf16.f32 "         \
                 "{%0,%1,%2,%3}, {%4,%5,%6,%7}, {%8,%9}, {%0,%1,%2,%3};"        \
                 : "+f"((d)[0]), "+f"((d)[1]), "+f"((d)[2]), "+f"((d)[3])       \
                 : "r"((a)[0]), "r"((a)[1]), "r"((a)[2]), "r"((a)[3]),          \
                   "r"(b0), "r"(b1))

// ---------------------------------------------------------------------------
__global__ void ln_kernel(const float* __restrict__ x,
                          const float* __restrict__ gamma,
                          const float* __restrict__ beta) {
    int b = blockIdx.x;
    const float* row = x + (size_t)b * D_;
    float s = 0.f, s2 = 0.f;
    for (int i = threadIdx.x; i < D_; i += blockDim.x) {
        float v = row[i];
        s += v; s2 += v * v;
    }
    __shared__ float red[64];
    for (int o = 16; o; o >>= 1) {
        s  += __shfl_down_sync(0xffffffffu, s,  o);
        s2 += __shfl_down_sync(0xffffffffu, s2, o);
    }
    int wid = threadIdx.x >> 5, lid = threadIdx.x & 31;
    if (lid == 0) { red[wid] = s; red[wid + 32] = s2; }
    __syncthreads();
    int nw = blockDim.x >> 5;
    if (wid == 0) {
        s  = (lid < nw) ? red[lid]      : 0.f;
        s2 = (lid < nw) ? red[lid + 32] : 0.f;
        for (int o = 16; o; o >>= 1) {
            s  += __shfl_down_sync(0xffffffffu, s,  o);
            s2 += __shfl_down_sync(0xffffffffu, s2, o);
        }
        if (lid == 0) { red[0] = s; red[1] = s2; }
    }
    __syncthreads();
    float mu   = red[0] / D_;
    float var  = red[1] / D_ - mu * mu;
    float rstd = rsqrtf(var + 1e-5f);
    for (int i = threadIdx.x; i < D_; i += blockDim.x) {
        float v = (row[i] - mu) * rstd * gamma[i] + beta[i];
        size_t idx = (size_t)b * D_ + i;
        __nv_bfloat16 hi, lo;
        splitbf(v, hi, lo);
        g_hhi[idx] = hi;
        g_hlo[idx] = lo;
    }
}

// ---------------------------------------------------------------------------
__global__ void transpose_split_kernel(const float* __restrict__ src,
                                       __nv_bfloat16* __restrict__ dhi,
                                       __nv_bfloat16* __restrict__ dlo,
                                       int R, int C) {
    __shared__ float t[32][33];
    int e = blockIdx.z;
    int c0 = blockIdx.x * 32, r0 = blockIdx.y * 32;
    const float* s = src + (size_t)e * R * C;
    #pragma unroll
    for (int i = 0; i < 32; i += 8)
        t[threadIdx.y + i][threadIdx.x] =
            s[(size_t)(r0 + threadIdx.y + i) * C + c0 + threadIdx.x];
    __syncthreads();
    size_t ob = (size_t)e * C * R;
    #pragma unroll
    for (int i = 0; i < 32; i += 8) {
        float v = t[threadIdx.x][threadIdx.y + i];
        __nv_bfloat16 hi, lo;
        splitbf(v, hi, lo);
        size_t o = ob + (size_t)(c0 + threadIdx.y + i) * R + r0 + threadIdx.x;
        dhi[o] = hi;
        dlo[o] = lo;
    }
}

// ---------------------------------------------------------------------------
// bf16x3 GEMM: 128x128x32 CTA, 8 warps of 64x32 (2Mx4N), 256 threads,
// 64B-pitch XOR-swizzled smem (seg ^= (row>>1)&3), 2-stage pipeline,
// 2 CTAs/SM -> 16 warps/SM (4/SMSP) for issue-stall hiding.
// OUT_MODE: 0 = fp32 +bias, 1 = fp32 gelu, 2 = gelu + bf16 hi/lo split
// ---------------------------------------------------------------------------
#define PLANE_B 8192                     // 128 rows * 64B
#define STAGE_B (4 * PLANE_B)            // Ahi|Alo|Bhi|Blo = 32768
#define NSTG 2
#define SMEM_TC (NSTG * STAGE_B)         // 65536

template <int OUT_MODE>
__global__ void __launch_bounds__(256, 2) gemm_bf16x3(
    const __nv_bfloat16* __restrict__ Ahi, const __nv_bfloat16* __restrict__ Alo,
    const __nv_bfloat16* __restrict__ Bhi, const __nv_bfloat16* __restrict__ Blo,
    const float* __restrict__ bias,
    __nv_bfloat16* __restrict__ OutHi, __nv_bfloat16* __restrict__ OutLo,
    float* __restrict__ OutF,
    int Ktot, size_t aStrideE, size_t bStrideE, size_t biasStrideE,
    size_t cStrideE, int ldc, int cColStride)
{
    extern __shared__ char smem[];
    uint32_t sbase = smem_to_u32(smem);
    int tid  = threadIdx.x;
    int warp = tid >> 5, lane = tid & 31;
    int e  = blockIdx.z;
    int bm = blockIdx.y * 128;
    int bn = blockIdx.x * 128;
    int wm = (warp >> 2) * 64;          // 2 warps along M
    int wn = (warp & 3)  * 32;          // 4 warps along N
    int g  = lane >> 2, tg = lane & 3;
    int mi = lane >> 3, rr = lane & 7;

    const __nv_bfloat16* pAhi = Ahi + (size_t)e * aStrideE + (size_t)bm * Ktot;
    const __nv_bfloat16* pAlo = Alo + (size_t)e * aStrideE + (size_t)bm * Ktot;
    const __nv_bfloat16* pBhi = Bhi + (size_t)e * bStrideE + (size_t)bn * Ktot;
    const __nv_bfloat16* pBlo = Blo + (size_t)e * bStrideE + (size_t)bn * Ktot;

    // ldmatrix lane addressing (64B pitch, swizzle seg ^= (row>>1)&3).
    // A x4 mats: (m0,k0),(m0+8,k0),(m0,k0+8),(m0+8,k0+8): row = wm+(mi&1)*8+rr,
    // k-seg = ks*2 + (mi>>1). Row steps of 16 across i keep the swizzle invariant.
    int arow = wm + (mi & 1) * 8 + rr;
    uint32_t aoff = (uint32_t)arow * 64;
    uint32_t aswz = (uint32_t)(((arow >> 1) & 3) << 4);
    int akseg = mi >> 1;
    // B x4 mats: (n0,k0),(n0,k0+8),(n0+8,k0),(n0+8,k0+8): row = wn+(mi>>1)*8+rr,
    // k-seg = ks*2 + (mi&1).
    int brow = wn + (mi >> 1) * 8 + rr;
    uint32_t boff = (uint32_t)brow * 64;
    uint32_t bswz = (uint32_t)(((brow >> 1) & 3) << 4);
    int bkseg = mi & 1;

    float acc[4][4][4];
    #pragma unroll
    for (int i = 0; i < 4; i++)
        #pragma unroll
        for (int j = 0; j < 4; j++)
            #pragma unroll
            for (int r = 0; r < 4; r++) acc[i][j][r] = 0.f;

    const int NC = Ktot / 32;

    auto load_chunk = [&](int c, int st) {
        int k0 = c * 32;
        uint32_t sb = sbase + (uint32_t)st * STAGE_B;
        #pragma unroll
        for (int i = 0; i < 2; i++) {            // 512 16B units per plane
            int p = tid + i * 256;
            int row = p >> 2, col = p & 3;
            uint32_t d = sb + (uint32_t)row * 64
                       + (uint32_t)((col ^ ((row >> 1) & 3)) << 4);
            size_t go = (size_t)row * Ktot + k0 + col * 8;
            cpa16(d,                 pAhi + go);
            cpa16(d + PLANE_B,       pAlo + go);
            cpa16(d + 2u * PLANE_B,  pBhi + go);
            cpa16(d + 3u * PLANE_B,  pBlo + go);
        }
        CP_COMMIT();
    };

    load_chunk(0, 0);
    if (NC > 1) load_chunk(1, 1);

    for (int c = 0; c < NC; c++) {
        if (c + 1 < NC) { CP_WAIT1(); } else { CP_WAIT0(); }
        __syncthreads();

        uint32_t sb = sbase + (uint32_t)((c % NSTG) * STAGE_B);
        #pragma unroll
        for (int ks = 0; ks < 2; ks++) {
            uint32_t ah[4][4], al[4][4], bh[2][4], bl[2][4];
            #pragma unroll
            for (int i = 0; i < 4; i++) {
                uint32_t ad = sb + aoff + (uint32_t)i * 1024
                            + (((uint32_t)(ks * 2 + akseg) << 4) ^ aswz);
                LDSM4(ah[i], ad);
                LDSM4(al[i], ad + PLANE_B);
            }
            #pragma unroll
            for (int jp = 0; jp < 2; jp++) {
                uint32_t bd = sb + 2u * PLANE_B + boff + (uint32_t)jp * 1024
                            + (((uint32_t)(ks * 2 + bkseg) << 4) ^ bswz);
                LDSM4(bh[jp], bd);
                LDSM4(bl[jp], bd + PLANE_B);
            }
            #pragma unroll
            for (int i = 0; i < 4; i++)
                #pragma unroll
                for (int j = 0; j < 4; j++) {
                    int jp = j >> 1, hf = (j & 1) * 2;
                    MMA_BF16(acc[i][j], ah[i], bh[jp][hf], bh[jp][hf + 1]);
                }
            #pragma unroll
            for (int i = 0; i < 4; i++)
                #pragma unroll
                for (int j = 0; j < 4; j++) {
                    int jp = j >> 1, hf = (j & 1) * 2;
                    MMA_BF16(acc[i][j], ah[i], bl[jp][hf], bl[jp][hf + 1]);
                }
            #pragma unroll
            for (int i = 0; i < 4; i++)
                #pragma unroll
                for (int j = 0; j < 4; j++) {
                    int jp = j >> 1, hf = (j & 1) * 2;
                    MMA_BF16(acc[i][j], al[i], bh[jp][hf], bh[jp][hf + 1]);
                }
        }
        __syncthreads();                          // stage fully consumed
        if (c + 2 < NC) load_chunk(c + 2, c % NSTG);
    }

    const float* bp = bias + (size_t)e * biasStrideE;
    #pragma unroll
    for (int i = 0; i < 4; i++) {
        int r0 = bm + wm + i * 16 + g;
        #pragma unroll
        for (int j = 0; j < 4; j++) {
            int c0 = bn + wn + j * 8 + tg * 2;
            float bi0 = bp[c0], bi1 = bp[c0 + 1];
            float v0 = acc[i][j][0] + bi0, v1 = acc[i][j][1] + bi1;
            float v2 = acc[i][j][2] + bi0, v3 = acc[i][j][3] + bi1;
            size_t rbA = (size_t)e * cStrideE + (size_t)r0 * ldc
                       + (size_t)e * cColStride + c0;
            size_t rbB = rbA + (size_t)8 * ldc;
            if (OUT_MODE == 0) {
                OutF[rbA] = v0; OutF[rbA + 1] = v1;
                OutF[rbB] = v2; OutF[rbB + 1] = v3;
            } else if (OUT_MODE == 1) {
                OutF[rbA] = geluf(v0); OutF[rbA + 1] = geluf(v1);
                OutF[rbB] = geluf(v2); OutF[rbB + 1] = geluf(v3);
            } else {
                v0 = geluf(v0); v1 = geluf(v1); v2 = geluf(v2); v3 = geluf(v3);
                __nv_bfloat16 h0, l0, h1, l1;
                splitbf(v0, h0, l0); splitbf(v1, h1, l1);
                *(uint32_t*)(OutHi + rbA) = pack2(h0, h1);
                *(uint32_t*)(OutLo + rbA) = pack2(l0, l1);
                splitbf(v2, h0, l0); splitbf(v3, h1, l1);
                *(uint32_t*)(OutHi + rbB) = pack2(h0, h1);
                *(uint32_t*)(OutLo + rbB) = pack2(l0, l1);
            }
        }
    }
}

// ---------------------------------------------------------------------------
__global__ void gate_kernel(const float* __restrict__ gw2,
                            const float* __restrict__ gb2,
                            float* __restrict__ dout) {
    int b = blockIdx.x * (blockDim.x >> 5) + (threadIdx.x >> 5);
    if (b >= B_) return;
    int lane = threadIdx.x & 31;
    int e = lane & 7, s = lane >> 3;

    const float* gr = g_g + (size_t)b * GH_;
    float acc = 0.f;
    int k0 = s * (GH_ / 4);
    #pragma unroll 4
    for (int k = k0; k < k0 + GH_ / 4; k++)
        acc = fmaf(gr[k], gw2[k * E_ + e], acc);
    acc += __shfl_xor_sync(0xffffffffu, acc, 8);
    acc += __shfl_xor_sync(0xffffffffu, acc, 16);
    float logit = acc + gb2[e];

    float m = logit;
    for (int o = 4; o; o >>= 1) m = fmaxf(m, __shfl_xor_sync(0xffffffffu, m, o));
    float p = (lane < E_) ? expf(logit - m) : 0.f;
    float ssum = p;
    for (int o = 16; o; o >>= 1) ssum += __shfl_xor_sync(0xffffffffu, ssum, o);
    float prob = p / ssum;
    if (lane < E_) dout[OFF_GATE + (size_t)b * E_ + lane] = prob;

    float v1 = (lane < E_) ? prob : -1.f; int i1 = lane;
    for (int o = 16; o; o >>= 1) {
        float ov = __shfl_xor_sync(0xffffffffu, v1, o);
        int   oi = __shfl_xor_sync(0xffffffffu, i1, o);
        if (ov > v1 || (ov == v1 && oi < i1)) { v1 = ov; i1 = oi; }
    }
    float v2 = (lane < E_ && lane != i1) ? prob : -1.f; int i2 = lane;
    for (int o = 16; o; o >>= 1) {
        float ov = __shfl_xor_sync(0xffffffffu, v2, o);
        int   oi = __shfl_xor_sync(0xffffffffu, i2, o);
        if (ov > v2 || (ov == v2 && oi < i2)) { v2 = ov; i2 = oi; }
    }
    if (lane == 0) {
        float sw = v1 + v2;
        g_tw[b * 2 + 0] = v1 / sw;
        g_tw[b * 2 + 1] = v2 / sw;
        g_ti[b * 2 + 0] = i1;
        g_ti[b * 2 + 1] = i2;
    }
}

// ---------------------------------------------------------------------------
__global__ void combine_kernel(float* __restrict__ dout) {
    size_t i = (size_t)blockIdx.x * blockDim.x + threadIdx.x;
    if (i >= (size_t)B_ * D_) return;
    int b = (int)(i / D_), d = (int)(i % D_);
    int   i0 = g_ti[b * 2], i1 = g_ti[b * 2 + 1];
    float w0 = g_tw[b * 2], w1 = g_tw[b * 2 + 1];
    const float* eo = dout + OFF_EO + (size_t)b * E_ * D_;
    dout[i] = w0 * eo[(size_t)i0 * D_ + d] + w1 * eo[(size_t)i1 * D_ + d];
}

// ---------------------------------------------------------------------------
extern "C" void kernel_launch(void* const* d_in, const int* in_sizes, int n_in,
                              void* d_out, int out_size) {
    const float* x     = (const float*)d_in[0];
    const float* gamma = (const float*)d_in[1];
    const float* beta  = (const float*)d_in[2];
    const float* gw1   = (const float*)d_in[3];
    const float* gb1   = (const float*)d_in[4];
    const float* gw2   = (const float*)d_in[5];
    const float* gb2   = (const float*)d_in[6];
    const float* ew1   = (const float*)d_in[7];
    const float* eb1   = (const float*)d_in[8];
    const float* ew2   = (const float*)d_in[9];
    const float* eb2   = (const float*)d_in[10];
    float* out = (float*)d_out;

    float *pg;
    __nv_bfloat16 *phhi, *phlo, *pgw1hi, *pgw1lo, *pw1hi, *pw1lo, *pw2hi, *pw2lo,
                  *phidhi, *phidlo;
    cudaGetSymbolAddress((void**)&pg,     g_g);
    cudaGetSymbolAddress((void**)&phhi,   g_hhi);
    cudaGetSymbolAddress((void**)&phlo,   g_hlo);
    cudaGetSymbolAddress((void**)&pgw1hi, g_gw1hi);
    cudaGetSymbolAddress((void**)&pgw1lo, g_gw1lo);
    cudaGetSymbolAddress((void**)&pw1hi,  g_w1hi);
    cudaGetSymbolAddress((void**)&pw1lo,  g_w1lo);
    cudaGetSymbolAddress((void**)&pw2hi,  g_w2hi);
    cudaGetSymbolAddress((void**)&pw2lo,  g_w2lo);
    cudaGetSymbolAddress((void**)&phidhi, g_hidhi);
    cudaGetSymbolAddress((void**)&phidlo, g_hidlo);

    cudaFuncSetAttribute(gemm_bf16x3<0>, cudaFuncAttributeMaxDynamicSharedMemorySize, SMEM_TC);
    cudaFuncSetAttribute(gemm_bf16x3<1>, cudaFuncAttributeMaxDynamicSharedMemorySize, SMEM_TC);
    cudaFuncSetAttribute(gemm_bf16x3<2>, cudaFuncAttributeMaxDynamicSharedMemorySize, SMEM_TC);

    // 1. LayerNorm + bf16 split
    ln_kernel<<<B_, 256>>>(x, gamma, beta);

    // 2-4. Weight transposes + splits (K-major [N,K] operands)
    transpose_split_kernel<<<dim3(H_ / 32, D_ / 32, E_), dim3(32, 8)>>>(ew1, pw1hi, pw1lo, D_, H_);
    transpose_split_kernel<<<dim3(D_ / 32, H_ / 32, E_), dim3(32, 8)>>>(ew2, pw2hi, pw2lo, H_, D_);
    transpose_split_kernel<<<dim3(GH_ / 32, D_ / 32, 1), dim3(32, 8)>>>(gw1, pgw1hi, pgw1lo, D_, GH_);

    // 5. Expert GEMM1: hid[e] = gelu(h @ ew1[e] + eb1[e]), bf16 split out
    gemm_bf16x3<2><<<dim3(H_ / 128, B_ / 128, E_), 256, SMEM_TC>>>(
        phhi, phlo, pw1hi, pw1lo, eb1,
        phidhi, phidlo, nullptr,
        D_, 0, (size_t)H_ * D_, H_,
        (size_t)B_ * H_, H_, 0);

    // 6. Expert GEMM2: expert_outputs[:,e,:] = hid[e] @ ew2[e] + eb2[e] (fp32)
    gemm_bf16x3<0><<<dim3(D_ / 128, B_ / 128, E_), 256, SMEM_TC>>>(
        phidhi, phidlo, pw2hi, pw2lo, eb2,
        nullptr, nullptr, out + OFF_EO,
        H_, (size_t)B_ * H_, (size_t)D_ * H_, D_,
        0, E_ * D_, D_);

    // 7. Gating layer1: g = gelu(h @ gw1 + gb1), fp32
    gemm_bf16x3<1><<<dim3(GH_ / 128, B_ / 128, 1), 256, SMEM_TC>>>(
        phhi, phlo, pgw1hi, pgw1lo, gb1,
        nullptr, nullptr, pg,
        D_, 0, 0, 0, 0, GH_, 0);

    // 8. Gate softmax + top-2
    gate_kernel<<<(B_ + 7) / 8, 256>>>(gw2, gb2, out);

    // 9. Combine -> result
    combine_kernel<<<((int)((size_t)B_ * D_ + 255) / 256), 256>>>(out);
}

// round 10
// speedup vs baseline: 3.0429x; 1.0027x over previous
#include <cuda_runtime.h>
#include <cuda_bf16.h>
#include <math.h>
#include <stdint.h>

#define B_  8192
#define D_  768
#define GH_ 384
#define E_  8
#define H_  3072

#define OFF_GATE ((size_t)B_ * D_)
#define OFF_EO   (OFF_GATE + (size_t)B_ * E_)

__device__ float g_g[(size_t)B_ * GH_];
__device__ __align__(16) __nv_bfloat16 g_hhi[(size_t)B_ * D_];
__device__ __align__(16) __nv_bfloat16 g_hlo[(size_t)B_ * D_];
__device__ __align__(16) __nv_bfloat16 g_gw1hi[(size_t)GH_ * D_];
__device__ __align__(16) __nv_bfloat16 g_gw1lo[(size_t)GH_ * D_];
__device__ __align__(16) __nv_bfloat16 g_w1hi[(size_t)E_ * H_ * D_];
__device__ __align__(16) __nv_bfloat16 g_w1lo[(size_t)E_ * H_ * D_];
__device__ __align__(16) __nv_bfloat16 g_w2hi[(size_t)E_ * D_ * H_];
__device__ __align__(16) __nv_bfloat16 g_w2lo[(size_t)E_ * D_ * H_];
__device__ __align__(16) __nv_bfloat16 g_hidhi[(size_t)E_ * B_ * H_];
__device__ __align__(16) __nv_bfloat16 g_hidlo[(size_t)E_ * B_ * H_];
__device__ float g_tw[B_ * 2];
__device__ int   g_ti[B_ * 2];

__device__ __forceinline__ uint32_t smem_to_u32(const void* p) {
    uint32_t a;
    asm("{ .reg .u64 t; cvta.to.shared.u64 t, %1; cvt.u32.u64 %0, t; }" : "=r"(a) : "l"(p));
    return a;
}
__device__ __forceinline__ float geluf(float x) {
    return 0.5f * x * (1.f + erff(x * 0.7071067811865475f));
}
__device__ __forceinline__ void splitbf(float v, __nv_bfloat16& h, __nv_bfloat16& l) {
    h = __float2bfloat16(v);
    l = __float2bfloat16(v - __bfloat162float(h));
}
__device__ __forceinline__ uint32_t pack2(__nv_bfloat16 a, __nv_bfloat16 b) {
    return (uint32_t)__bfloat16_as_ushort(a) | ((uint32_t)__bfloat16_as_ushort(b) << 16);
}
__device__ __forceinline__ void cpa16(uint32_t dst, const void* src) {
    asm volatile("cp.async.cg.shared.global [%0], [%1], 16;" :: "r"(dst), "l"(src));
}
#define CP_COMMIT() asm volatile("cp.async.commit_group;" ::: "memory")
#define CP_WAIT1()  asm volatile("cp.async.wait_group 1;" ::: "memory")
#define CP_WAIT0()  asm volatile("cp.async.wait_group 0;" ::: "memory")

#define LDSM4(r, addr)                                                          \
    asm volatile("ldmatrix.sync.aligned.m8n8.x4.shared.b16 {%0,%1,%2,%3}, [%4];"\
                 : "=r"((r)[0]), "=r"((r)[1]), "=r"((r)[2]), "=r"((r)[3])       \
                 : "r"(addr))

#define MMA_BF16(d, a, b0, b1)                                                  \
    asm volatile("mma.sync.aligned.m16n8k16.row.col.f32.bf16.bf16.f32 "         \
                 "{%0,%1,%2,%3}, {%4,%5,%6,%7}, {%8,%9}, {%0,%1,%2,%3};"        \
                 : "+f"((d)[0]), "+f"((d)[1]), "+f"((d)[2]), "+f"((d)[3])       \
                 : "r"((a)[0]), "r"((a)[1]), "r"((a)[2]), "r"((a)[3]),          \
                   "r"(b0), "r"(b1))

// ---------------------------------------------------------------------------
__global__ void ln_kernel(const float* __restrict__ x,
                          const float* __restrict__ gamma,
                          const float* __restrict__ beta) {
    int b = blockIdx.x;
    const float* row = x + (size_t)b * D_;
    float s = 0.f, s2 = 0.f;
    for (int i = threadIdx.x; i < D_; i += blockDim.x) {
        float v = row[i];
        s += v; s2 += v * v;
    }
    __shared__ float red[64];
    for (int o = 16; o; o >>= 1) {
        s  += __shfl_down_sync(0xffffffffu, s,  o);
        s2 += __shfl_down_sync(0xffffffffu, s2, o);
    }
    int wid = threadIdx.x >> 5, lid = threadIdx.x & 31;
    if (lid == 0) { red[wid] = s; red[wid + 32] = s2; }
    __syncthreads();
    int nw = blockDim.x >> 5;
    if (wid == 0) {
        s  = (lid < nw) ? red[lid]      : 0.f;
        s2 = (lid < nw) ? red[lid + 32] : 0.f;
        for (int o = 16; o; o >>= 1) {
            s  += __shfl_down_sync(0xffffffffu, s,  o);
            s2 += __shfl_down_sync(0xffffffffu, s2, o);
        }
        if (lid == 0) { red[0] = s; red[1] = s2; }
    }
    __syncthreads();
    float mu   = red[0] / D_;
    float var  = red[1] / D_ - mu * mu;
    float rstd = rsqrtf(var + 1e-5f);
    for (int i = threadIdx.x; i < D_; i += blockDim.x) {
        float v = (row[i] - mu) * rstd * gamma[i] + beta[i];
        size_t idx = (size_t)b * D_ + i;
        __nv_bfloat16 hi, lo;
        splitbf(v, hi, lo);
        g_hhi[idx] = hi;
        g_hlo[idx] = lo;
    }
}

// ---------------------------------------------------------------------------
__global__ void transpose_split_kernel(const float* __restrict__ src,
                                       __nv_bfloat16* __restrict__ dhi,
                                       __nv_bfloat16* __restrict__ dlo,
                                       int R, int C) {
    __shared__ float t[32][33];
    int e = blockIdx.z;
    int c0 = blockIdx.x * 32, r0 = blockIdx.y * 32;
    const float* s = src + (size_t)e * R * C;
    #pragma unroll
    for (int i = 0; i < 32; i += 8)
        t[threadIdx.y + i][threadIdx.x] =
            s[(size_t)(r0 + threadIdx.y + i) * C + c0 + threadIdx.x];
    __syncthreads();
    size_t ob = (size_t)e * C * R;
    #pragma unroll
    for (int i = 0; i < 32; i += 8) {
        float v = t[threadIdx.x][threadIdx.y + i];
        __nv_bfloat16 hi, lo;
        splitbf(v, hi, lo);
        size_t o = ob + (size_t)(c0 + threadIdx.y + i) * R + r0 + threadIdx.x;
        dhi[o] = hi;
        dlo[o] = lo;
    }
}

// ---------------------------------------------------------------------------
// bf16x3 GEMM: 128x128x32 CTA, 8 warps of 64x32 (2Mx4N), 256 threads,
// 64B-pitch XOR-swizzled smem, 3-stage pipeline with ONE barrier per chunk
// (stage for chunk c+2 was consumed in iter c-1, ordered by this iter's sync),
// loads issued BEFORE compute. 2 CTAs/SM (192 KB smem) -> 16 warps/SM.
// OUT_MODE: 0 = fp32 +bias, 1 = fp32 gelu, 2 = gelu + bf16 hi/lo split
// ---------------------------------------------------------------------------
#define PLANE_B 8192                     // 128 rows * 64B
#define STAGE_B (4 * PLANE_B)            // Ahi|Alo|Bhi|Blo = 32768
#define NSTG 3
#define SMEM_TC (NSTG * STAGE_B)         // 98304

template <int OUT_MODE>
__global__ void __launch_bounds__(256, 2) gemm_bf16x3(
    const __nv_bfloat16* __restrict__ Ahi, const __nv_bfloat16* __restrict__ Alo,
    const __nv_bfloat16* __restrict__ Bhi, const __nv_bfloat16* __restrict__ Blo,
    const float* __restrict__ bias,
    __nv_bfloat16* __restrict__ OutHi, __nv_bfloat16* __restrict__ OutLo,
    float* __restrict__ OutF,
    int Ktot, size_t aStrideE, size_t bStrideE, size_t biasStrideE,
    size_t cStrideE, int ldc, int cColStride)
{
    extern __shared__ char smem[];
    uint32_t sbase = smem_to_u32(smem);
    int tid  = threadIdx.x;
    int warp = tid >> 5, lane = tid & 31;
    int e  = blockIdx.z;
    int bm = blockIdx.y * 128;
    int bn = blockIdx.x * 128;
    int wm = (warp >> 2) * 64;          // 2 warps along M
    int wn = (warp & 3)  * 32;          // 4 warps along N
    int g  = lane >> 2, tg = lane & 3;
    int mi = lane >> 3, rr = lane & 7;

    const __nv_bfloat16* pAhi = Ahi + (size_t)e * aStrideE + (size_t)bm * Ktot;
    const __nv_bfloat16* pAlo = Alo + (size_t)e * aStrideE + (size_t)bm * Ktot;
    const __nv_bfloat16* pBhi = Bhi + (size_t)e * bStrideE + (size_t)bn * Ktot;
    const __nv_bfloat16* pBlo = Blo + (size_t)e * bStrideE + (size_t)bn * Ktot;

    int arow = wm + (mi & 1) * 8 + rr;
    uint32_t aoff = (uint32_t)arow * 64;
    uint32_t aswz = (uint32_t)(((arow >> 1) & 3) << 4);
    int akseg = mi >> 1;
    int brow = wn + (mi >> 1) * 8 + rr;
    uint32_t boff = (uint32_t)brow * 64;
    uint32_t bswz = (uint32_t)(((brow >> 1) & 3) << 4);
    int bkseg = mi & 1;

    float acc[4][4][4];
    #pragma unroll
    for (int i = 0; i < 4; i++)
        #pragma unroll
        for (int j = 0; j < 4; j++)
            #pragma unroll
            for (int r = 0; r < 4; r++) acc[i][j][r] = 0.f;

    const int NC = Ktot / 32;

    auto load_chunk = [&](int c, int st) {
        int k0 = c * 32;
        uint32_t sb = sbase + (uint32_t)st * STAGE_B;
        #pragma unroll
        for (int i = 0; i < 2; i++) {            // 512 16B units per plane
            int p = tid + i * 256;
            int row = p >> 2, col = p & 3;
            uint32_t d = sb + (uint32_t)row * 64
                       + (uint32_t)((col ^ ((row >> 1) & 3)) << 4);
            size_t go = (size_t)row * Ktot + k0 + col * 8;
            cpa16(d,                 pAhi + go);
            cpa16(d + PLANE_B,       pAlo + go);
            cpa16(d + 2u * PLANE_B,  pBhi + go);
            cpa16(d + 3u * PLANE_B,  pBlo + go);
        }
        CP_COMMIT();
    };

    load_chunk(0, 0);
    if (NC > 1) load_chunk(1, 1);

    for (int c = 0; c < NC; c++) {
        if (c + 1 < NC) { CP_WAIT1(); } else { CP_WAIT0(); }
        __syncthreads();
        // Chunk c resident. Stage (c+2)%3 was consumed in iter c-1 (ordered by
        // the sync above) -> safe to refill now, overlapping with this compute.
        if (c + 2 < NC) load_chunk(c + 2, (c + 2) % NSTG);

        uint32_t sb = sbase + (uint32_t)((c % NSTG) * STAGE_B);
        #pragma unroll
        for (int ks = 0; ks < 2; ks++) {
            uint32_t ah[4][4], al[4][4], bh[2][4], bl[2][4];
            #pragma unroll
            for (int i = 0; i < 4; i++) {
                uint32_t ad = sb + aoff + (uint32_t)i * 1024
                            + (((uint32_t)(ks * 2 + akseg) << 4) ^ aswz);
                LDSM4(ah[i], ad);
                LDSM4(al[i], ad + PLANE_B);
            }
            #pragma unroll
            for (int jp = 0; jp < 2; jp++) {
                uint32_t bd = sb + 2u * PLANE_B + boff + (uint32_t)jp * 1024
                            + (((uint32_t)(ks * 2 + bkseg) << 4) ^ bswz);
                LDSM4(bh[jp], bd);
                LDSM4(bl[jp], bd + PLANE_B);
            }
            #pragma unroll
            for (int i = 0; i < 4; i++)
                #pragma unroll
                for (int j = 0; j < 4; j++) {
                    int jp = j >> 1, hf = (j & 1) * 2;
                    MMA_BF16(acc[i][j], ah[i], bh[jp][hf], bh[jp][hf + 1]);
                }
            #pragma unroll
            for (int i = 0; i < 4; i++)
                #pragma unroll
                for (int j = 0; j < 4; j++) {
                    int jp = j >> 1, hf = (j & 1) * 2;
                    MMA_BF16(acc[i][j], ah[i], bl[jp][hf], bl[jp][hf + 1]);
                }
            #pragma unroll
            for (int i = 0; i < 4; i++)
                #pragma unroll
                for (int j = 0; j < 4; j++) {
                    int jp = j >> 1, hf = (j & 1) * 2;
                    MMA_BF16(acc[i][j], al[i], bh[jp][hf], bh[jp][hf + 1]);
                }
        }
    }

    const float* bp = bias + (size_t)e * biasStrideE;
    #pragma unroll
    for (int i = 0; i < 4; i++) {
        int r0 = bm + wm + i * 16 + g;
        #pragma unroll
        for (int j = 0; j < 4; j++) {
            int c0 = bn + wn + j * 8 + tg * 2;
            float bi0 = bp[c0], bi1 = bp[c0 + 1];
            float v0 = acc[i][j][0] + bi0, v1 = acc[i][j][1] + bi1;
            float v2 = acc[i][j][2] + bi0, v3 = acc[i][j][3] + bi1;
            size_t rbA = (size_t)e * cStrideE + (size_t)r0 * ldc
                       + (size_t)e * cColStride + c0;
            size_t rbB = rbA + (size_t)8 * ldc;
            if (OUT_MODE == 0) {
                OutF[rbA] = v0; OutF[rbA + 1] = v1;
                OutF[rbB] = v2; OutF[rbB + 1] = v3;
            } else if (OUT_MODE == 1) {
                OutF[rbA] = geluf(v0); OutF[rbA + 1] = geluf(v1);
                OutF[rbB] = geluf(v2); OutF[rbB + 1] = geluf(v3);
            } else {
                v0 = geluf(v0); v1 = geluf(v1); v2 = geluf(v2); v3 = geluf(v3);
                __nv_bfloat16 h0, l0, h1, l1;
                splitbf(v0, h0, l0); splitbf(v1, h1, l1);
                *(uint32_t*)(OutHi + rbA) = pack2(h0, h1);
                *(uint32_t*)(OutLo + rbA) = pack2(l0, l1);
                splitbf(v2, h0, l0); splitbf(v3, h1, l1);
                *(uint32_t*)(OutHi + rbB) = pack2(h0, h1);
                *(uint32_t*)(OutLo + rbB) = pack2(l0, l1);
            }
        }
    }
}

// ---------------------------------------------------------------------------
__global__ void gate_kernel(const float* __restrict__ gw2,
                            const float* __restrict__ gb2,
                            float* __restrict__ dout) {
    int b = blockIdx.x * (blockDim.x >> 5) + (threadIdx.x >> 5);
    if (b >= B_) return;
    int lane = threadIdx.x & 31;
    int e = lane & 7, s = lane >> 3;

    const float* gr = g_g + (size_t)b * GH_;
    float acc = 0.f;
    int k0 = s * (GH_ / 4);
    #pragma unroll 4
    for (int k = k0; k < k0 + GH_ / 4; k++)
        acc = fmaf(gr[k], gw2[k * E_ + e], acc);
    acc += __shfl_xor_sync(0xffffffffu, acc, 8);
    acc += __shfl_xor_sync(0xffffffffu, acc, 16);
    float logit = acc + gb2[e];

    float m = logit;
    for (int o = 4; o; o >>= 1) m = fmaxf(m, __shfl_xor_sync(0xffffffffu, m, o));
    float p = (lane < E_) ? expf(logit - m) : 0.f;
    float ssum = p;
    for (int o = 16; o; o >>= 1) ssum += __shfl_xor_sync(0xffffffffu, ssum, o);
    float prob = p / ssum;
    if (lane < E_) dout[OFF_GATE + (size_t)b * E_ + lane] = prob;

    float v1 = (lane < E_) ? prob : -1.f; int i1 = lane;
    for (int o = 16; o; o >>= 1) {
        float ov = __shfl_xor_sync(0xffffffffu, v1, o);
        int   oi = __shfl_xor_sync(0xffffffffu, i1, o);
        if (ov > v1 || (ov == v1 && oi < i1)) { v1 = ov; i1 = oi; }
    }
    float v2 = (lane < E_ && lane != i1) ? prob : -1.f; int i2 = lane;
    for (int o = 16; o; o >>= 1) {
        float ov = __shfl_xor_sync(0xffffffffu, v2, o);
        int   oi = __shfl_xor_sync(0xffffffffu, i2, o);
        if (ov > v2 || (ov == v2 && oi < i2)) { v2 = ov; i2 = oi; }
    }
    if (lane == 0) {
        float sw = v1 + v2;
        g_tw[b * 2 + 0] = v1 / sw;
        g_tw[b * 2 + 1] = v2 / sw;
        g_ti[b * 2 + 0] = i1;
        g_ti[b * 2 + 1] = i2;
    }
}

// ---------------------------------------------------------------------------
__global__ void combine_kernel(float* __restrict__ dout) {
    size_t i = (size_t)blockIdx.x * blockDim.x + threadIdx.x;
    if (i >= (size_t)B_ * D_) return;
    int b = (int)(i / D_), d = (int)(i % D_);
    int   i0 = g_ti[b * 2], i1 = g_ti[b * 2 + 1];
    float w0 = g_tw[b * 2], w1 = g_tw[b * 2 + 1];
    const float* eo = dout + OFF_EO + (size_t)b * E_ * D_;
    dout[i] = w0 * eo[(size_t)i0 * D_ + d] + w1 * eo[(size_t)i1 * D_ + d];
}

// ---------------------------------------------------------------------------
extern "C" void kernel_launch(void* const* d_in, const int* in_sizes, int n_in,
                              void* d_out, int out_size) {
    const float* x     = (const float*)d_in[0];
    const float* gamma = (const float*)d_in[1];
    const float* beta  = (const float*)d_in[2];
    const float* gw1   = (const float*)d_in[3];
    const float* gb1   = (const float*)d_in[4];
    const float* gw2   = (const float*)d_in[5];
    const float* gb2   = (const float*)d_in[6];
    const float* ew1   = (const float*)d_in[7];
    const float* eb1   = (const float*)d_in[8];
    const float* ew2   = (const float*)d_in[9];
    const float* eb2   = (const float*)d_in[10];
    float* out = (float*)d_out;

    float *pg;
    __nv_bfloat16 *phhi, *phlo, *pgw1hi, *pgw1lo, *pw1hi, *pw1lo, *pw2hi, *pw2lo,
                  *phidhi, *phidlo;
    cudaGetSymbolAddress((void**)&pg,     g_g);
    cudaGetSymbolAddress((void**)&phhi,   g_hhi);
    cudaGetSymbolAddress((void**)&phlo,   g_hlo);
    cudaGetSymbolAddress((void**)&pgw1hi, g_gw1hi);
    cudaGetSymbolAddress((void**)&pgw1lo, g_gw1lo);
    cudaGetSymbolAddress((void**)&pw1hi,  g_w1hi);
    cudaGetSymbolAddress((void**)&pw1lo,  g_w1lo);
    cudaGetSymbolAddress((void**)&pw2hi,  g_w2hi);
    cudaGetSymbolAddress((void**)&pw2lo,  g_w2lo);
    cudaGetSymbolAddress((void**)&phidhi, g_hidhi);
    cudaGetSymbolAddress((void**)&phidlo, g_hidlo);

    cudaFuncSetAttribute(gemm_bf16x3<0>, cudaFuncAttributeMaxDynamicSharedMemorySize, SMEM_TC);
    cudaFuncSetAttribute(gemm_bf16x3<1>, cudaFuncAttributeMaxDynamicSharedMemorySize, SMEM_TC);
    cudaFuncSetAttribute(gemm_bf16x3<2>, cudaFuncAttributeMaxDynamicSharedMemorySize, SMEM_TC);

    // 1. LayerNorm + bf16 split
    ln_kernel<<<B_, 256>>>(x, gamma, beta);

    // 2-4. Weight transposes + splits (K-major [N,K] operands)
    transpose_split_kernel<<<dim3(H_ / 32, D_ / 32, E_), dim3(32, 8)>>>(ew1, pw1hi, pw1lo, D_, H_);
    transpose_split_kernel<<<dim3(D_ / 32, H_ / 32, E_), dim3(32, 8)>>>(ew2, pw2hi, pw2lo, H_, D_);
    transpose_split_kernel<<<dim3(GH_ / 32, D_ / 32, 1), dim3(32, 8)>>>(gw1, pgw1hi, pgw1lo, D_, GH_);

    // 5. Expert GEMM1: hid[e] = gelu(h @ ew1[e] + eb1[e]), bf16 split out
    gemm_bf16x3<2><<<dim3(H_ / 128, B_ / 128, E_), 256, SMEM_TC>>>(
        phhi, phlo, pw1hi, pw1lo, eb1,
        phidhi, phidlo, nullptr,
        D_, 0, (size_t)H_ * D_, H_,
        (size_t)B_ * H_, H_, 0);

    // 6. Expert GEMM2: expert_outputs[:,e,:] = hid[e] @ ew2[e] + eb2[e] (fp32)
    gemm_bf16x3<0><<<dim3(D_ / 128, B_ / 128, E_), 256, SMEM_TC>>>(
        phidhi, phidlo, pw2hi, pw2lo, eb2,
        nullptr, nullptr, out + OFF_EO,
        H_, (size_t)B_ * H_, (size_t)D_ * H_, D_,
        0, E_ * D_, D_);

    // 7. Gating layer1: g = gelu(h @ gw1 + gb1), fp32
    gemm_bf16x3<1><<<dim3(GH_ / 128, B_ / 128, 1), 256, SMEM_TC>>>(
        phhi, phlo, pgw1hi, pgw1lo, gb1,
        nullptr, nullptr, pg,
        D_, 0, 0, 0, 0, GH_, 0);

    // 8. Gate softmax + top-2
    gate_kernel<<<(B_ + 7) / 8, 256>>>(gw2, gb2, out);

    // 9. Combine -> result
    combine_kernel<<<((int)((size_t)B_ * D_ + 255) / 256), 256>>>(out);
}

// round 11
// speedup vs baseline: 3.0938x; 1.0167x over previous
#include <cuda_runtime.h>
#include <cuda_bf16.h>
#include <math.h>
#include <stdint.h>

#define B_  8192
#define D_  768
#define GH_ 384
#define E_  8
#define H_  3072

#define OFF_GATE ((size_t)B_ * D_)
#define OFF_EO   (OFF_GATE + (size_t)B_ * E_)

__device__ float g_g[(size_t)B_ * GH_];
__device__ __align__(16) __nv_bfloat16 g_hhi[(size_t)B_ * D_];
__device__ __align__(16) __nv_bfloat16 g_hlo[(size_t)B_ * D_];
__device__ __align__(16) __nv_bfloat16 g_gw1hi[(size_t)GH_ * D_];
__device__ __align__(16) __nv_bfloat16 g_gw1lo[(size_t)GH_ * D_];
__device__ __align__(16) __nv_bfloat16 g_w1hi[(size_t)E_ * H_ * D_];
__device__ __align__(16) __nv_bfloat16 g_w1lo[(size_t)E_ * H_ * D_];
__device__ __align__(16) __nv_bfloat16 g_w2hi[(size_t)E_ * D_ * H_];
__device__ __align__(16) __nv_bfloat16 g_w2lo[(size_t)E_ * D_ * H_];
__device__ __align__(16) __nv_bfloat16 g_hidhi[(size_t)E_ * B_ * H_];
__device__ __align__(16) __nv_bfloat16 g_hidlo[(size_t)E_ * B_ * H_];
__device__ float g_tw[B_ * 2];
__device__ int   g_ti[B_ * 2];

__device__ __forceinline__ uint32_t smem_to_u32(const void* p) {
    uint32_t a;
    asm("{ .reg .u64 t; cvta.to.shared.u64 t, %1; cvt.u32.u64 %0, t; }" : "=r"(a) : "l"(p));
    return a;
}
// Fast exact-form gelu: A&S 7.1.26 erf approximation (abs err 1.5e-7).
__device__ __forceinline__ float gelu_fast(float x) {
    float xs = x * 0.7071067811865476f;
    float ax = fabsf(xs);
    float t  = __fdividef(1.0f, fmaf(0.3275911f, ax, 1.0f));
    float y  = t * fmaf(t, fmaf(t, fmaf(t, fmaf(t, 1.061405429f, -1.453152027f),
                                        1.421413741f), -0.284496736f), 0.254829592f);
    float ev = 1.0f - y * __expf(-ax * ax);
    ev = copysignf(ev, xs);
    return 0.5f * x * (1.0f + ev);
}
__device__ __forceinline__ void splitbf(float v, __nv_bfloat16& h, __nv_bfloat16& l) {
    h = __float2bfloat16(v);
    l = __float2bfloat16(v - __bfloat162float(h));
}
// Packed split: 2 fp32 -> hi bf16x2 word + lo bf16x2 word (lo = residuals).
__device__ __forceinline__ void split2(float v0, float v1, uint32_t& phi, uint32_t& plo) {
    uint32_t p;
    asm("cvt.rn.bf16x2.f32 %0, %1, %2;" : "=r"(p) : "f"(v1), "f"(v0));
    float h0 = __uint_as_float(p << 16);
    float h1 = __uint_as_float(p & 0xFFFF0000u);
    float r0 = v0 - h0, r1 = v1 - h1;
    uint32_t q;
    asm("cvt.rn.bf16x2.f32 %0, %1, %2;" : "=r"(q) : "f"(r1), "f"(r0));
    phi = p; plo = q;
}
__device__ __forceinline__ void cpa16(uint32_t dst, const void* src) {
    asm volatile("cp.async.cg.shared.global [%0], [%1], 16;" :: "r"(dst), "l"(src));
}
#define CP_COMMIT() asm volatile("cp.async.commit_group;" ::: "memory")
#define CP_WAIT1()  asm volatile("cp.async.wait_group 1;" ::: "memory")
#define CP_WAIT0()  asm volatile("cp.async.wait_group 0;" ::: "memory")

#define LDSM4(r, addr)                                                          \
    asm volatile("ldmatrix.sync.aligned.m8n8.x4.shared.b16 {%0,%1,%2,%3}, [%4];"\
                 : "=r"((r)[0]), "=r"((r)[1]), "=r"((r)[2]), "=r"((r)[3])       \
                 : "r"(addr))

#define MMA_BF16(d, a, b0, b1)                                                  \
    asm volatile("mma.sync.aligned.m16n8k16.row.col.f32.bf16.bf16.f32 "         \
                 "{%0,%1,%2,%3}, {%4,%5,%6,%7}, {%8,%9}, {%0,%1,%2,%3};"        \
                 : "+f"((d)[0]), "+f"((d)[1]), "+f"((d)[2]), "+f"((d)[3])       \
                 : "r"((a)[0]), "r"((a)[1]), "r"((a)[2]), "r"((a)[3]),          \
                   "r"(b0), "r"(b1))

// ---------------------------------------------------------------------------
__global__ void ln_kernel(const float* __restrict__ x,
                          const float* __restrict__ gamma,
                          const float* __restrict__ beta) {
    int b = blockIdx.x;
    const float* row = x + (size_t)b * D_;
    float s = 0.f, s2 = 0.f;
    for (int i = threadIdx.x; i < D_; i += blockDim.x) {
        float v = row[i];
        s += v; s2 += v * v;
    }
    __shared__ float red[64];
    for (int o = 16; o; o >>= 1) {
        s  += __shfl_down_sync(0xffffffffu, s,  o);
        s2 += __shfl_down_sync(0xffffffffu, s2, o);
    }
    int wid = threadIdx.x >> 5, lid = threadIdx.x & 31;
    if (lid == 0) { red[wid] = s; red[wid + 32] = s2; }
    __syncthreads();
    int nw = blockDim.x >> 5;
    if (wid == 0) {
        s  = (lid < nw) ? red[lid]      : 0.f;
        s2 = (lid < nw) ? red[lid + 32] : 0.f;
        for (int o = 16; o; o >>= 1) {
            s  += __shfl_down_sync(0xffffffffu, s,  o);
            s2 += __shfl_down_sync(0xffffffffu, s2, o);
        }
        if (lid == 0) { red[0] = s; red[1] = s2; }
    }
    __syncthreads();
    float mu   = red[0] / D_;
    float var  = red[1] / D_ - mu * mu;
    float rstd = rsqrtf(var + 1e-5f);
    for (int i = threadIdx.x; i < D_; i += blockDim.x) {
        float v = (row[i] - mu) * rstd * gamma[i] + beta[i];
        size_t idx = (size_t)b * D_ + i;
        __nv_bfloat16 hi, lo;
        splitbf(v, hi, lo);
        g_hhi[idx] = hi;
        g_hlo[idx] = lo;
    }
}

// ---------------------------------------------------------------------------
__global__ void transpose_split_kernel(const float* __restrict__ src,
                                       __nv_bfloat16* __restrict__ dhi,
                                       __nv_bfloat16* __restrict__ dlo,
                                       int R, int C) {
    __shared__ float t[32][33];
    int e = blockIdx.z;
    int c0 = blockIdx.x * 32, r0 = blockIdx.y * 32;
    const float* s = src + (size_t)e * R * C;
    #pragma unroll
    for (int i = 0; i < 32; i += 8)
        t[threadIdx.y + i][threadIdx.x] =
            s[(size_t)(r0 + threadIdx.y + i) * C + c0 + threadIdx.x];
    __syncthreads();
    size_t ob = (size_t)e * C * R;
    #pragma unroll
    for (int i = 0; i < 32; i += 8) {
        float v = t[threadIdx.x][threadIdx.y + i];
        __nv_bfloat16 hi, lo;
        splitbf(v, hi, lo);
        size_t o = ob + (size_t)(c0 + threadIdx.y + i) * R + r0 + threadIdx.x;
        dhi[o] = hi;
        dlo[o] = lo;
    }
}

// ---------------------------------------------------------------------------
__global__ void zero_kernel(float* __restrict__ p, size_t n4) {
    size_t i = (size_t)blockIdx.x * blockDim.x + threadIdx.x;
    if (i < n4) ((float4*)p)[i] = make_float4(0.f, 0.f, 0.f, 0.f);
}

// ---------------------------------------------------------------------------
// bf16x3 GEMM: 128x128x32 CTA, 8 warps of 64x32 (2Mx4N), 256 threads,
// 64B-pitch XOR-swizzled smem, 3-stage pipeline, 2 CTAs/SM -> 16 warps/SM.
// OUT_MODE: 1 = fp32 gelu (gating), 2 = gelu + bf16 hi/lo split (GEMM1),
//           3 = fp32 +bias + fused top-k combine atomics (GEMM2)
// ---------------------------------------------------------------------------
#define PLANE_B 8192                     // 128 rows * 64B
#define STAGE_B (4 * PLANE_B)            // Ahi|Alo|Bhi|Blo = 32768
#define NSTG 3
#define SMEM_TC (NSTG * STAGE_B)         // 98304

template <int OUT_MODE>
__global__ void __launch_bounds__(256, 2) gemm_bf16x3(
    const __nv_bfloat16* __restrict__ Ahi, const __nv_bfloat16* __restrict__ Alo,
    const __nv_bfloat16* __restrict__ Bhi, const __nv_bfloat16* __restrict__ Blo,
    const float* __restrict__ bias,
    __nv_bfloat16* __restrict__ OutHi, __nv_bfloat16* __restrict__ OutLo,
    float* __restrict__ OutF, float* __restrict__ Res,
    int Ktot, size_t aStrideE, size_t bStrideE, size_t biasStrideE,
    size_t cStrideE, int ldc, int cColStride)
{
    extern __shared__ char smem[];
    uint32_t sbase = smem_to_u32(smem);
    int tid  = threadIdx.x;
    int warp = tid >> 5, lane = tid & 31;
    int e  = blockIdx.z;
    int bm = blockIdx.y * 128;
    int bn = blockIdx.x * 128;
    int wm = (warp >> 2) * 64;          // 2 warps along M
    int wn = (warp & 3)  * 32;          // 4 warps along N
    int g  = lane >> 2, tg = lane & 3;
    int mi = lane >> 3, rr = lane & 7;

    const __nv_bfloat16* pAhi = Ahi + (size_t)e * aStrideE + (size_t)bm * Ktot;
    const __nv_bfloat16* pAlo = Alo + (size_t)e * aStrideE + (size_t)bm * Ktot;
    const __nv_bfloat16* pBhi = Bhi + (size_t)e * bStrideE + (size_t)bn * Ktot;
    const __nv_bfloat16* pBlo = Blo + (size_t)e * bStrideE + (size_t)bn * Ktot;

    int arow = wm + (mi & 1) * 8 + rr;
    uint32_t aoff = (uint32_t)arow * 64;
    uint32_t aswz = (uint32_t)(((arow >> 1) & 3) << 4);
    int akseg = mi >> 1;
    int brow = wn + (mi >> 1) * 8 + rr;
    uint32_t boff = (uint32_t)brow * 64;
    uint32_t bswz = (uint32_t)(((brow >> 1) & 3) << 4);
    int bkseg = mi & 1;

    float acc[4][4][4];
    #pragma unroll
    for (int i = 0; i < 4; i++)
        #pragma unroll
        for (int j = 0; j < 4; j++)
            #pragma unroll
            for (int r = 0; r < 4; r++) acc[i][j][r] = 0.f;

    const int NC = Ktot / 32;

    auto load_chunk = [&](int c, int st) {
        int k0 = c * 32;
        uint32_t sb = sbase + (uint32_t)st * STAGE_B;
        #pragma unroll
        for (int i = 0; i < 2; i++) {            // 512 16B units per plane
            int p = tid + i * 256;
            int row = p >> 2, col = p & 3;
            uint32_t d = sb + (uint32_t)row * 64
                       + (uint32_t)((col ^ ((row >> 1) & 3)) << 4);
            size_t go = (size_t)row * Ktot + k0 + col * 8;
            cpa16(d,                 pAhi + go);
            cpa16(d + PLANE_B,       pAlo + go);
            cpa16(d + 2u * PLANE_B,  pBhi + go);
            cpa16(d + 3u * PLANE_B,  pBlo + go);
        }
        CP_COMMIT();
    };

    load_chunk(0, 0);
    if (NC > 1) load_chunk(1, 1);

    for (int c = 0; c < NC; c++) {
        if (c + 1 < NC) { CP_WAIT1(); } else { CP_WAIT0(); }
        __syncthreads();
        if (c + 2 < NC) load_chunk(c + 2, (c + 2) % NSTG);

        uint32_t sb = sbase + (uint32_t)((c % NSTG) * STAGE_B);
        #pragma unroll
        for (int ks = 0; ks < 2; ks++) {
            uint32_t ah[4][4], al[4][4], bh[2][4], bl[2][4];
            #pragma unroll
            for (int i = 0; i < 4; i++) {
                uint32_t ad = sb + aoff + (uint32_t)i * 1024
                            + (((uint32_t)(ks * 2 + akseg) << 4) ^ aswz);
                LDSM4(ah[i], ad);
                LDSM4(al[i], ad + PLANE_B);
            }
            #pragma unroll
            for (int jp = 0; jp < 2; jp++) {
                uint32_t bd = sb + 2u * PLANE_B + boff + (uint32_t)jp * 1024
                            + (((uint32_t)(ks * 2 + bkseg) << 4) ^ bswz);
                LDSM4(bh[jp], bd);
                LDSM4(bl[jp], bd + PLANE_B);
            }
            #pragma unroll
            for (int i = 0; i < 4; i++)
                #pragma unroll
                for (int j = 0; j < 4; j++) {
                    int jp = j >> 1, hf = (j & 1) * 2;
                    MMA_BF16(acc[i][j], ah[i], bh[jp][hf], bh[jp][hf + 1]);
                }
            #pragma unroll
            for (int i = 0; i < 4; i++)
                #pragma unroll
                for (int j = 0; j < 4; j++) {
                    int jp = j >> 1, hf = (j & 1) * 2;
                    MMA_BF16(acc[i][j], ah[i], bl[jp][hf], bl[jp][hf + 1]);
                }
            #pragma unroll
            for (int i = 0; i < 4; i++)
                #pragma unroll
                for (int j = 0; j < 4; j++) {
                    int jp = j >> 1, hf = (j & 1) * 2;
                    MMA_BF16(acc[i][j], al[i], bh[jp][hf], bh[jp][hf + 1]);
                }
        }
    }

    const float* bp = bias + (size_t)e * biasStrideE;
    #pragma unroll
    for (int i = 0; i < 4; i++) {
        int r0 = bm + wm + i * 16 + g;
        // fused-combine weights for the 2 rows this i covers (OUT_MODE 3)
        float cw0 = 0.f, cw1 = 0.f;
        if (OUT_MODE == 3) {
            int i00 = g_ti[r0 * 2], i01 = g_ti[r0 * 2 + 1];
            cw0 = (i00 == e) ? g_tw[r0 * 2] : ((i01 == e) ? g_tw[r0 * 2 + 1] : 0.f);
            int r1 = r0 + 8;
            int i10 = g_ti[r1 * 2], i11 = g_ti[r1 * 2 + 1];
            cw1 = (i10 == e) ? g_tw[r1 * 2] : ((i11 == e) ? g_tw[r1 * 2 + 1] : 0.f);
        }
        #pragma unroll
        for (int j = 0; j < 4; j++) {
            int c0 = bn + wn + j * 8 + tg * 2;
            float bi0 = bp[c0], bi1 = bp[c0 + 1];
            float v0 = acc[i][j][0] + bi0, v1 = acc[i][j][1] + bi1;
            float v2 = acc[i][j][2] + bi0, v3 = acc[i][j][3] + bi1;
            size_t rbA = (size_t)e * cStrideE + (size_t)r0 * ldc
                       + (size_t)e * cColStride + c0;
            size_t rbB = rbA + (size_t)8 * ldc;
            if (OUT_MODE == 3) {
                OutF[rbA] = v0; OutF[rbA + 1] = v1;
                OutF[rbB] = v2; OutF[rbB + 1] = v3;
                if (cw0 != 0.f) {
                    atomicAdd(&Res[(size_t)r0 * D_ + c0],     cw0 * v0);
                    atomicAdd(&Res[(size_t)r0 * D_ + c0 + 1], cw0 * v1);
                }
                if (cw1 != 0.f) {
                    atomicAdd(&Res[(size_t)(r0 + 8) * D_ + c0],     cw1 * v2);
                    atomicAdd(&Res[(size_t)(r0 + 8) * D_ + c0 + 1], cw1 * v3);
                }
            } else if (OUT_MODE == 1) {
                OutF[rbA] = gelu_fast(v0); OutF[rbA + 1] = gelu_fast(v1);
                OutF[rbB] = gelu_fast(v2); OutF[rbB + 1] = gelu_fast(v3);
            } else {  // OUT_MODE 2
                v0 = gelu_fast(v0); v1 = gelu_fast(v1);
                v2 = gelu_fast(v2); v3 = gelu_fast(v3);
                uint32_t phi, plo;
                split2(v0, v1, phi, plo);
                *(uint32_t*)(OutHi + rbA) = phi;
                *(uint32_t*)(OutLo + rbA) = plo;
                split2(v2, v3, phi, plo);
                *(uint32_t*)(OutHi + rbB) = phi;
                *(uint32_t*)(OutLo + rbB) = plo;
            }
        }
    }
}

// ---------------------------------------------------------------------------
__global__ void gate_kernel(const float* __restrict__ gw2,
                            const float* __restrict__ gb2,
                            float* __restrict__ dout) {
    int b = blockIdx.x * (blockDim.x >> 5) + (threadIdx.x >> 5);
    if (b >= B_) return;
    int lane = threadIdx.x & 31;
    int e = lane & 7, s = lane >> 3;

    const float* gr = g_g + (size_t)b * GH_;
    float acc = 0.f;
    int k0 = s * (GH_ / 4);
    #pragma unroll 4
    for (int k = k0; k < k0 + GH_ / 4; k++)
        acc = fmaf(gr[k], gw2[k * E_ + e], acc);
    acc += __shfl_xor_sync(0xffffffffu, acc, 8);
    acc += __shfl_xor_sync(0xffffffffu, acc, 16);
    float logit = acc + gb2[e];

    float m = logit;
    for (int o = 4; o; o >>= 1) m = fmaxf(m, __shfl_xor_sync(0xffffffffu, m, o));
    float p = (lane < E_) ? expf(logit - m) : 0.f;
    float ssum = p;
    for (int o = 16; o; o >>= 1) ssum += __shfl_xor_sync(0xffffffffu, ssum, o);
    float prob = p / ssum;
    if (lane < E_) dout[OFF_GATE + (size_t)b * E_ + lane] = prob;

    float v1 = (lane < E_) ? prob : -1.f; int i1 = lane;
    for (int o = 16; o; o >>= 1) {
        float ov = __shfl_xor_sync(0xffffffffu, v1, o);
        int   oi = __shfl_xor_sync(0xffffffffu, i1, o);
        if (ov > v1 || (ov == v1 && oi < i1)) { v1 = ov; i1 = oi; }
    }
    float v2 = (lane < E_ && lane != i1) ? prob : -1.f; int i2 = lane;
    for (int o = 16; o; o >>= 1) {
        float ov = __shfl_xor_sync(0xffffffffu, v2, o);
        int   oi = __shfl_xor_sync(0xffffffffu, i2, o);
        if (ov > v2 || (ov == v2 && oi < i2)) { v2 = ov; i2 = oi; }
    }
    if (lane == 0) {
        float sw = v1 + v2;
        g_tw[b * 2 + 0] = v1 / sw;
        g_tw[b * 2 + 1] = v2 / sw;
        g_ti[b * 2 + 0] = i1;
        g_ti[b * 2 + 1] = i2;
    }
}

// ---------------------------------------------------------------------------
extern "C" void kernel_launch(void* const* d_in, const int* in_sizes, int n_in,
                              void* d_out, int out_size) {
    const float* x     = (const float*)d_in[0];
    const float* gamma = (const float*)d_in[1];
    const float* beta  = (const float*)d_in[2];
    const float* gw1   = (const float*)d_in[3];
    const float* gb1   = (const float*)d_in[4];
    const float* gw2   = (const float*)d_in[5];
    const float* gb2   = (const float*)d_in[6];
    const float* ew1   = (const float*)d_in[7];
    const float* eb1   = (const float*)d_in[8];
    const float* ew2   = (const float*)d_in[9];
    const float* eb2   = (const float*)d_in[10];
    float* out = (float*)d_out;

    float *pg;
    __nv_bfloat16 *phhi, *phlo, *pgw1hi, *pgw1lo, *pw1hi, *pw1lo, *pw2hi, *pw2lo,
                  *phidhi, *phidlo;
    cudaGetSymbolAddress((void**)&pg,     g_g);
    cudaGetSymbolAddress((void**)&phhi,   g_hhi);
    cudaGetSymbolAddress((void**)&phlo,   g_hlo);
    cudaGetSymbolAddress((void**)&pgw1hi, g_gw1hi);
    cudaGetSymbolAddress((void**)&pgw1lo, g_gw1lo);
    cudaGetSymbolAddress((void**)&pw1hi,  g_w1hi);
    cudaGetSymbolAddress((void**)&pw1lo,  g_w1lo);
    cudaGetSymbolAddress((void**)&pw2hi,  g_w2hi);
    cudaGetSymbolAddress((void**)&pw2lo,  g_w2lo);
    cudaGetSymbolAddress((void**)&phidhi, g_hidhi);
    cudaGetSymbolAddress((void**)&phidlo, g_hidlo);

    cudaFuncSetAttribute(gemm_bf16x3<1>, cudaFuncAttributeMaxDynamicSharedMemorySize, SMEM_TC);
    cudaFuncSetAttribute(gemm_bf16x3<2>, cudaFuncAttributeMaxDynamicSharedMemorySize, SMEM_TC);
    cudaFuncSetAttribute(gemm_bf16x3<3>, cudaFuncAttributeMaxDynamicSharedMemorySize, SMEM_TC);

    // 1. LayerNorm + bf16 split
    ln_kernel<<<B_, 256>>>(x, gamma, beta);

    // 2. ew1 transpose + split
    transpose_split_kernel<<<dim3(H_ / 32, D_ / 32, E_), dim3(32, 8)>>>(ew1, pw1hi, pw1lo, D_, H_);

    // 3. Expert GEMM1: hid[e] = gelu(h @ ew1[e] + eb1[e]), bf16 split out
    gemm_bf16x3<2><<<dim3(H_ / 128, B_ / 128, E_), 256, SMEM_TC>>>(
        phhi, phlo, pw1hi, pw1lo, eb1,
        phidhi, phidlo, nullptr, nullptr,
        D_, 0, (size_t)H_ * D_, H_,
        (size_t)B_ * H_, H_, 0);

    // 4. Gating path: gw1 transpose, gating GEMM, softmax/top-2
    transpose_split_kernel<<<dim3(GH_ / 32, D_ / 32, 1), dim3(32, 8)>>>(gw1, pgw1hi, pgw1lo, D_, GH_);
    gemm_bf16x3<1><<<dim3(GH_ / 128, B_ / 128, 1), 256, SMEM_TC>>>(
        phhi, phlo, pgw1hi, pgw1lo, gb1,
        nullptr, nullptr, pg, nullptr,
        D_, 0, 0, 0, 0, GH_, 0);
    gate_kernel<<<(B_ + 7) / 8, 256>>>(gw2, gb2, out);

    // 5. ew2 transpose + zero result region (for fused-combine atomics)
    transpose_split_kernel<<<dim3(D_ / 32, H_ / 32, E_), dim3(32, 8)>>>(ew2, pw2hi, pw2lo, H_, D_);
    zero_kernel<<<(int)(((size_t)B_ * D_ / 4 + 255) / 256), 256>>>(out, (size_t)B_ * D_ / 4);

    // 6. Expert GEMM2 + fused top-k combine: EO = hid @ ew2 + eb2;
    //    result += w_e * EO for selected experts (2 commutative atomic adds/elt)
    gemm_bf16x3<3><<<dim3(D_ / 128, B_ / 128, E_), 256, SMEM_TC>>>(
        phidhi, phidlo, pw2hi, pw2lo, eb2,
        nullptr, nullptr, out + OFF_EO, out,
        H_, (size_t)B_ * H_, (size_t)D_ * H_, D_,
        0, E_ * D_, D_);
}

// round 12
// speedup vs baseline: 7.1306x; 2.3048x over previous
#include <cuda_runtime.h>
#include <cuda_bf16.h>
#include <cuda_fp16.h>
#include <math.h>
#include <stdint.h>

#define B_  8192
#define D_  768
#define GH_ 384
#define E_  8
#define H_  3072

#define OFF_GATE ((size_t)B_ * D_)
#define OFF_EO   (OFF_GATE + (size_t)B_ * E_)

// Scratch
__device__ float g_g[(size_t)B_ * GH_];
__device__ __align__(16) __nv_bfloat16 g_hhi[(size_t)B_ * D_];   // gating path (exact)
__device__ __align__(16) __nv_bfloat16 g_hlo[(size_t)B_ * D_];
__device__ __align__(16) __nv_bfloat16 g_gw1hi[(size_t)GH_ * D_];
__device__ __align__(16) __nv_bfloat16 g_gw1lo[(size_t)GH_ * D_];
__device__ __align__(16) __half g_hf[(size_t)B_ * D_];           // fp16 expert path
__device__ __align__(16) __half g_w1f[(size_t)E_ * H_ * D_];
__device__ __align__(16) __half g_w2f[(size_t)E_ * D_ * H_];
__device__ __align__(16) __half g_hidf[(size_t)E_ * B_ * H_];
__device__ float g_tw[B_ * 2];
__device__ int   g_ti[B_ * 2];

__device__ __forceinline__ uint32_t smem_to_u32(const void* p) {
    uint32_t a;
    asm("{ .reg .u64 t; cvta.to.shared.u64 t, %1; cvt.u32.u64 %0, t; }" : "=r"(a) : "l"(p));
    return a;
}
// Fast exact-form gelu (A&S 7.1.26 erf, abs err 1.5e-7)
__device__ __forceinline__ float gelu_fast(float x) {
    float xs = x * 0.7071067811865476f;
    float ax = fabsf(xs);
    float t  = __fdividef(1.0f, fmaf(0.3275911f, ax, 1.0f));
    float y  = t * fmaf(t, fmaf(t, fmaf(t, fmaf(t, 1.061405429f, -1.453152027f),
                                        1.421413741f), -0.284496736f), 0.254829592f);
    float ev = 1.0f - y * __expf(-ax * ax);
    ev = copysignf(ev, xs);
    return 0.5f * x * (1.0f + ev);
}
__device__ __forceinline__ void splitbf(float v, __nv_bfloat16& h, __nv_bfloat16& l) {
    h = __float2bfloat16(v);
    l = __float2bfloat16(v - __bfloat162float(h));
}
__device__ __forceinline__ uint32_t packh2(float v0, float v1) {
    uint32_t p;
    asm("cvt.rn.f16x2.f32 %0, %1, %2;" : "=r"(p) : "f"(v1), "f"(v0));
    return p;  // lo half = v0
}
__device__ __forceinline__ void cpa16(uint32_t dst, const void* src) {
    asm volatile("cp.async.cg.shared.global [%0], [%1], 16;" :: "r"(dst), "l"(src));
}
#define CP_COMMIT() asm volatile("cp.async.commit_group;" ::: "memory")
#define CP_WAIT2()  asm volatile("cp.async.wait_group 2;" ::: "memory")
#define CP_WAIT1()  asm volatile("cp.async.wait_group 1;" ::: "memory")
#define CP_WAIT0()  asm volatile("cp.async.wait_group 0;" ::: "memory")

#define LDSM4(r, addr)                                                          \
    asm volatile("ldmatrix.sync.aligned.m8n8.x4.shared.b16 {%0,%1,%2,%3}, [%4];"\
                 : "=r"((r)[0]), "=r"((r)[1]), "=r"((r)[2]), "=r"((r)[3])       \
                 : "r"(addr))

#define MMA_BF16(d, a, b0, b1)                                                  \
    asm volatile("mma.sync.aligned.m16n8k16.row.col.f32.bf16.bf16.f32 "         \
                 "{%0,%1,%2,%3}, {%4,%5,%6,%7}, {%8,%9}, {%0,%1,%2,%3};"        \
                 : "+f"((d)[0]), "+f"((d)[1]), "+f"((d)[2]), "+f"((d)[3])       \
                 : "r"((a)[0]), "r"((a)[1]), "r"((a)[2]), "r"((a)[3]),          \
                   "r"(b0), "r"(b1))

#define MMA_F16(d, a, b0, b1)                                                   \
    asm volatile("mma.sync.aligned.m16n8k16.row.col.f32.f16.f16.f32 "           \
                 "{%0,%1,%2,%3}, {%4,%5,%6,%7}, {%8,%9}, {%0,%1,%2,%3};"        \
                 : "+f"((d)[0]), "+f"((d)[1]), "+f"((d)[2]), "+f"((d)[3])       \
                 : "r"((a)[0]), "r"((a)[1]), "r"((a)[2]), "r"((a)[3]),          \
                   "r"(b0), "r"(b1))

// ---------------------------------------------------------------------------
// LayerNorm: bf16 hi/lo (gating) + fp16 single plane (experts)
// ---------------------------------------------------------------------------
__global__ void ln_kernel(const float* __restrict__ x,
                          const float* __restrict__ gamma,
                          const float* __restrict__ beta) {
    int b = blockIdx.x;
    const float* row = x + (size_t)b * D_;
    float s = 0.f, s2 = 0.f;
    for (int i = threadIdx.x; i < D_; i += blockDim.x) {
        float v = row[i];
        s += v; s2 += v * v;
    }
    __shared__ float red[64];
    for (int o = 16; o; o >>= 1) {
        s  += __shfl_down_sync(0xffffffffu, s,  o);
        s2 += __shfl_down_sync(0xffffffffu, s2, o);
    }
    int wid = threadIdx.x >> 5, lid = threadIdx.x & 31;
    if (lid == 0) { red[wid] = s; red[wid + 32] = s2; }
    __syncthreads();
    int nw = blockDim.x >> 5;
    if (wid == 0) {
        s  = (lid < nw) ? red[lid]      : 0.f;
        s2 = (lid < nw) ? red[lid + 32] : 0.f;
        for (int o = 16; o; o >>= 1) {
            s  += __shfl_down_sync(0xffffffffu, s,  o);
            s2 += __shfl_down_sync(0xffffffffu, s2, o);
        }
        if (lid == 0) { red[0] = s; red[1] = s2; }
    }
    __syncthreads();
    float mu   = red[0] / D_;
    float var  = red[1] / D_ - mu * mu;
    float rstd = rsqrtf(var + 1e-5f);
    for (int i = threadIdx.x; i < D_; i += blockDim.x) {
        float v = (row[i] - mu) * rstd * gamma[i] + beta[i];
        size_t idx = (size_t)b * D_ + i;
        __nv_bfloat16 hi, lo;
        splitbf(v, hi, lo);
        g_hhi[idx] = hi;
        g_hlo[idx] = lo;
        g_hf[idx]  = __float2half_rn(v);
    }
}

// ---------------------------------------------------------------------------
// Transposes: fp16 single-plane (expert weights) and bf16 split (gating)
// ---------------------------------------------------------------------------
__global__ void transpose_f16_kernel(const float* __restrict__ src,
                                     __half* __restrict__ dst, int R, int C) {
    __shared__ float t[32][33];
    int e = blockIdx.z;
    int c0 = blockIdx.x * 32, r0 = blockIdx.y * 32;
    const float* s = src + (size_t)e * R * C;
    #pragma unroll
    for (int i = 0; i < 32; i += 8)
        t[threadIdx.y + i][threadIdx.x] =
            s[(size_t)(r0 + threadIdx.y + i) * C + c0 + threadIdx.x];
    __syncthreads();
    size_t ob = (size_t)e * C * R;
    #pragma unroll
    for (int i = 0; i < 32; i += 8)
        dst[ob + (size_t)(c0 + threadIdx.y + i) * R + r0 + threadIdx.x] =
            __float2half_rn(t[threadIdx.x][threadIdx.y + i]);
}

__global__ void transpose_split_kernel(const float* __restrict__ src,
                                       __nv_bfloat16* __restrict__ dhi,
                                       __nv_bfloat16* __restrict__ dlo,
                                       int R, int C) {
    __shared__ float t[32][33];
    int c0 = blockIdx.x * 32, r0 = blockIdx.y * 32;
    #pragma unroll
    for (int i = 0; i < 32; i += 8)
        t[threadIdx.y + i][threadIdx.x] =
            src[(size_t)(r0 + threadIdx.y + i) * C + c0 + threadIdx.x];
    __syncthreads();
    #pragma unroll
    for (int i = 0; i < 32; i += 8) {
        float v = t[threadIdx.x][threadIdx.y + i];
        __nv_bfloat16 hi, lo;
        splitbf(v, hi, lo);
        size_t o = (size_t)(c0 + threadIdx.y + i) * R + r0 + threadIdx.x;
        dhi[o] = hi;
        dlo[o] = lo;
    }
}

__global__ void zero_kernel(float* __restrict__ p, size_t n4) {
    size_t i = (size_t)blockIdx.x * blockDim.x + threadIdx.x;
    if (i < n4) ((float4*)p)[i] = make_float4(0.f, 0.f, 0.f, 0.f);
}

// ---------------------------------------------------------------------------
// fp16 single-plane GEMM: 128x128x32 CTA, 8 warps 64x32, 256 thr,
// 64B-pitch XOR-swizzled smem, 4-stage pipeline, 2 CTAs/SM.
// OUT_MODE: 2 = gelu + fp16 out (GEMM1), 3 = fp32 +bias + fused combine (GEMM2)
// ---------------------------------------------------------------------------
#define FPLANE 8192                      // 128 rows * 64B
#define FSTAGE (2 * FPLANE)              // A|B = 16384
#define FNSTG 4
#define SMEM_F (FNSTG * FSTAGE)          // 65536

template <int OUT_MODE>
__global__ void __launch_bounds__(256, 2) gemm_f16(
    const __half* __restrict__ Ah, const __half* __restrict__ Bh,
    const float* __restrict__ bias,
    __half* __restrict__ OutH, float* __restrict__ OutF, float* __restrict__ Res,
    int Ktot, size_t aStrideE, size_t bStrideE, size_t biasStrideE,
    size_t cStrideE, int ldc, int cColStride)
{
    extern __shared__ char smem[];
    uint32_t sbase = smem_to_u32(smem);
    int tid  = threadIdx.x;
    int warp = tid >> 5, lane = tid & 31;
    int e  = blockIdx.z;
    int bm = blockIdx.y * 128;
    int bn = blockIdx.x * 128;
    int wm = (warp >> 2) * 64;
    int wn = (warp & 3)  * 32;
    int g  = lane >> 2, tg = lane & 3;
    int mi = lane >> 3, rr = lane & 7;

    const __half* pA = Ah + (size_t)e * aStrideE + (size_t)bm * Ktot;
    const __half* pB = Bh + (size_t)e * bStrideE + (size_t)bn * Ktot;

    int arow = wm + (mi & 1) * 8 + rr;
    uint32_t aoff = (uint32_t)arow * 64;
    uint32_t aswz = (uint32_t)(((arow >> 1) & 3) << 4);
    int akseg = mi >> 1;
    int brow = wn + (mi >> 1) * 8 + rr;
    uint32_t boff = (uint32_t)brow * 64;
    uint32_t bswz = (uint32_t)(((brow >> 1) & 3) << 4);
    int bkseg = mi & 1;

    float acc[4][4][4];
    #pragma unroll
    for (int i = 0; i < 4; i++)
        #pragma unroll
        for (int j = 0; j < 4; j++)
            #pragma unroll
            for (int r = 0; r < 4; r++) acc[i][j][r] = 0.f;

    const int NC = Ktot / 32;

    auto load_chunk = [&](int c, int st) {
        int k0 = c * 32;
        uint32_t sb = sbase + (uint32_t)st * FSTAGE;
        #pragma unroll
        for (int i = 0; i < 2; i++) {            // 512 16B units per plane
            int p = tid + i * 256;
            int row = p >> 2, col = p & 3;
            uint32_t d = sb + (uint32_t)row * 64
                       + (uint32_t)((col ^ ((row >> 1) & 3)) << 4);
            size_t go = (size_t)row * Ktot + k0 + col * 8;
            cpa16(d,          pA + go);
            cpa16(d + FPLANE, pB + go);
        }
        CP_COMMIT();
    };

    load_chunk(0, 0);
    if (NC > 1) load_chunk(1, 1);
    if (NC > 2) load_chunk(2, 2);

    for (int c = 0; c < NC; c++) {
        if (c + 2 < NC)      { CP_WAIT2(); }
        else if (c + 1 < NC) { CP_WAIT1(); }
        else                 { CP_WAIT0(); }
        __syncthreads();
        if (c + 3 < NC) load_chunk(c + 3, (c + 3) % FNSTG);

        uint32_t sb = sbase + (uint32_t)((c % FNSTG) * FSTAGE);
        #pragma unroll
        for (int ks = 0; ks < 2; ks++) {
            uint32_t af[4][4], bf[2][4];
            #pragma unroll
            for (int i = 0; i < 4; i++) {
                uint32_t ad = sb + aoff + (uint32_t)i * 1024
                            + (((uint32_t)(ks * 2 + akseg) << 4) ^ aswz);
                LDSM4(af[i], ad);
            }
            #pragma unroll
            for (int jp = 0; jp < 2; jp++) {
                uint32_t bd = sb + FPLANE + boff + (uint32_t)jp * 1024
                            + (((uint32_t)(ks * 2 + bkseg) << 4) ^ bswz);
                LDSM4(bf[jp], bd);
            }
            #pragma unroll
            for (int i = 0; i < 4; i++)
                #pragma unroll
                for (int j = 0; j < 4; j++) {
                    int jp = j >> 1, hf = (j & 1) * 2;
                    MMA_F16(acc[i][j], af[i], bf[jp][hf], bf[jp][hf + 1]);
                }
        }
    }

    const float* bp = bias + (size_t)e * biasStrideE;
    #pragma unroll
    for (int i = 0; i < 4; i++) {
        int r0 = bm + wm + i * 16 + g;
        float cw0 = 0.f, cw1 = 0.f;
        if (OUT_MODE == 3) {
            int i00 = g_ti[r0 * 2], i01 = g_ti[r0 * 2 + 1];
            cw0 = (i00 == e) ? g_tw[r0 * 2] : ((i01 == e) ? g_tw[r0 * 2 + 1] : 0.f);
            int r1 = r0 + 8;
            int i10 = g_ti[r1 * 2], i11 = g_ti[r1 * 2 + 1];
            cw1 = (i10 == e) ? g_tw[r1 * 2] : ((i11 == e) ? g_tw[r1 * 2 + 1] : 0.f);
        }
        #pragma unroll
        for (int j = 0; j < 4; j++) {
            int c0 = bn + wn + j * 8 + tg * 2;
            float bi0 = bp[c0], bi1 = bp[c0 + 1];
            float v0 = acc[i][j][0] + bi0, v1 = acc[i][j][1] + bi1;
            float v2 = acc[i][j][2] + bi0, v3 = acc[i][j][3] + bi1;
            size_t rbA = (size_t)e * cStrideE + (size_t)r0 * ldc
                       + (size_t)e * cColStride + c0;
            size_t rbB = rbA + (size_t)8 * ldc;
            if (OUT_MODE == 3) {
                OutF[rbA] = v0; OutF[rbA + 1] = v1;
                OutF[rbB] = v2; OutF[rbB + 1] = v3;
                if (cw0 != 0.f) {
                    atomicAdd(&Res[(size_t)r0 * D_ + c0],     cw0 * v0);
                    atomicAdd(&Res[(size_t)r0 * D_ + c0 + 1], cw0 * v1);
                }
                if (cw1 != 0.f) {
                    atomicAdd(&Res[(size_t)(r0 + 8) * D_ + c0],     cw1 * v2);
                    atomicAdd(&Res[(size_t)(r0 + 8) * D_ + c0 + 1], cw1 * v3);
                }
            } else {  // OUT_MODE 2: gelu + fp16
                v0 = gelu_fast(v0); v1 = gelu_fast(v1);
                v2 = gelu_fast(v2); v3 = gelu_fast(v3);
                *(uint32_t*)(OutH + rbA) = packh2(v0, v1);
                *(uint32_t*)(OutH + rbB) = packh2(v2, v3);
            }
        }
    }
}

// ---------------------------------------------------------------------------
// Exact bf16x3 gating GEMM (unchanged math, gelu fp32 out)
// ---------------------------------------------------------------------------
#define PLANE_B 8192
#define STAGE_B (4 * PLANE_B)
#define NSTG 3
#define SMEM_TC (NSTG * STAGE_B)

__global__ void __launch_bounds__(256, 2) gemm_gate(
    const __nv_bfloat16* __restrict__ Ahi, const __nv_bfloat16* __restrict__ Alo,
    const __nv_bfloat16* __restrict__ Bhi, const __nv_bfloat16* __restrict__ Blo,
    const float* __restrict__ bias, float* __restrict__ OutF,
    int Ktot, int ldc)
{
    extern __shared__ char smem[];
    uint32_t sbase = smem_to_u32(smem);
    int tid  = threadIdx.x;
    int warp = tid >> 5, lane = tid & 31;
    int bm = blockIdx.y * 128;
    int bn = blockIdx.x * 128;
    int wm = (warp >> 2) * 64;
    int wn = (warp & 3)  * 32;
    int g  = lane >> 2, tg = lane & 3;
    int mi = lane >> 3, rr = lane & 7;

    const __nv_bfloat16* pAhi = Ahi + (size_t)bm * Ktot;
    const __nv_bfloat16* pAlo = Alo + (size_t)bm * Ktot;
    const __nv_bfloat16* pBhi = Bhi + (size_t)bn * Ktot;
    const __nv_bfloat16* pBlo = Blo + (size_t)bn * Ktot;

    int arow = wm + (mi & 1) * 8 + rr;
    uint32_t aoff = (uint32_t)arow * 64;
    uint32_t aswz = (uint32_t)(((arow >> 1) & 3) << 4);
    int akseg = mi >> 1;
    int brow = wn + (mi >> 1) * 8 + rr;
    uint32_t boff = (uint32_t)brow * 64;
    uint32_t bswz = (uint32_t)(((brow >> 1) & 3) << 4);
    int bkseg = mi & 1;

    float acc[4][4][4];
    #pragma unroll
    for (int i = 0; i < 4; i++)
        #pragma unroll
        for (int j = 0; j < 4; j++)
            #pragma unroll
            for (int r = 0; r < 4; r++) acc[i][j][r] = 0.f;

    const int NC = Ktot / 32;

    auto load_chunk = [&](int c, int st) {
        int k0 = c * 32;
        uint32_t sb = sbase + (uint32_t)st * STAGE_B;
        #pragma unroll
        for (int i = 0; i < 2; i++) {
            int p = tid + i * 256;
            int row = p >> 2, col = p & 3;
            uint32_t d = sb + (uint32_t)row * 64
                       + (uint32_t)((col ^ ((row >> 1) & 3)) << 4);
            size_t go = (size_t)row * Ktot + k0 + col * 8;
            cpa16(d,                 pAhi + go);
            cpa16(d + PLANE_B,       pAlo + go);
            cpa16(d + 2u * PLANE_B,  pBhi + go);
            cpa16(d + 3u * PLANE_B,  pBlo + go);
        }
        CP_COMMIT();
    };

    load_chunk(0, 0);
    if (NC > 1) load_chunk(1, 1);

    for (int c = 0; c < NC; c++) {
        if (c + 1 < NC) { CP_WAIT1(); } else { CP_WAIT0(); }
        __syncthreads();
        if (c + 2 < NC) load_chunk(c + 2, (c + 2) % NSTG);

        uint32_t sb = sbase + (uint32_t)((c % NSTG) * STAGE_B);
        #pragma unroll
        for (int ks = 0; ks < 2; ks++) {
            uint32_t ah[4][4], al[4][4], bh[2][4], bl[2][4];
            #pragma unroll
            for (int i = 0; i < 4; i++) {
                uint32_t ad = sb + aoff + (uint32_t)i * 1024
                            + (((uint32_t)(ks * 2 + akseg) << 4) ^ aswz);
                LDSM4(ah[i], ad);
                LDSM4(al[i], ad + PLANE_B);
            }
            #pragma unroll
            for (int jp = 0; jp < 2; jp++) {
                uint32_t bd = sb + 2u * PLANE_B + boff + (uint32_t)jp * 1024
                            + (((uint32_t)(ks * 2 + bkseg) << 4) ^ bswz);
                LDSM4(bh[jp], bd);
                LDSM4(bl[jp], bd + PLANE_B);
            }
            #pragma unroll
            for (int i = 0; i < 4; i++)
                #pragma unroll
                for (int j = 0; j < 4; j++) {
                    int jp = j >> 1, hf = (j & 1) * 2;
                    MMA_BF16(acc[i][j], ah[i], bh[jp][hf], bh[jp][hf + 1]);
                }
            #pragma unroll
            for (int i = 0; i < 4; i++)
                #pragma unroll
                for (int j = 0; j < 4; j++) {
                    int jp = j >> 1, hf = (j & 1) * 2;
                    MMA_BF16(acc[i][j], ah[i], bl[jp][hf], bl[jp][hf + 1]);
                }
            #pragma unroll
            for (int i = 0; i < 4; i++)
                #pragma unroll
                for (int j = 0; j < 4; j++) {
                    int jp = j >> 1, hf = (j & 1) * 2;
                    MMA_BF16(acc[i][j], al[i], bh[jp][hf], bh[jp][hf + 1]);
                }
        }
    }

    #pragma unroll
    for (int i = 0; i < 4; i++) {
        int r0 = bm + wm + i * 16 + g;
        #pragma unroll
        for (int j = 0; j < 4; j++) {
            int c0 = bn + wn + j * 8 + tg * 2;
            float bi0 = bias[c0], bi1 = bias[c0 + 1];
            size_t rbA = (size_t)r0 * ldc + c0;
            size_t rbB = rbA + (size_t)8 * ldc;
            OutF[rbA]     = gelu_fast(acc[i][j][0] + bi0);
            OutF[rbA + 1] = gelu_fast(acc[i][j][1] + bi1);
            OutF[rbB]     = gelu_fast(acc[i][j][2] + bi0);
            OutF[rbB + 1] = gelu_fast(acc[i][j][3] + bi1);
        }
    }
}

// ---------------------------------------------------------------------------
__global__ void gate_kernel(const float* __restrict__ gw2,
                            const float* __restrict__ gb2,
                            float* __restrict__ dout) {
    int b = blockIdx.x * (blockDim.x >> 5) + (threadIdx.x >> 5);
    if (b >= B_) return;
    int lane = threadIdx.x & 31;
    int e = lane & 7, s = lane >> 3;

    const float* gr = g_g + (size_t)b * GH_;
    float acc = 0.f;
    int k0 = s * (GH_ / 4);
    #pragma unroll 4
    for (int k = k0; k < k0 + GH_ / 4; k++)
        acc = fmaf(gr[k], gw2[k * E_ + e], acc);
    acc += __shfl_xor_sync(0xffffffffu, acc, 8);
    acc += __shfl_xor_sync(0xffffffffu, acc, 16);
    float logit = acc + gb2[e];

    float m = logit;
    for (int o = 4; o; o >>= 1) m = fmaxf(m, __shfl_xor_sync(0xffffffffu, m, o));
    float p = (lane < E_) ? expf(logit - m) : 0.f;
    float ssum = p;
    for (int o = 16; o; o >>= 1) ssum += __shfl_xor_sync(0xffffffffu, ssum, o);
    float prob = p / ssum;
    if (lane < E_) dout[OFF_GATE + (size_t)b * E_ + lane] = prob;

    float v1 = (lane < E_) ? prob : -1.f; int i1 = lane;
    for (int o = 16; o; o >>= 1) {
        float ov = __shfl_xor_sync(0xffffffffu, v1, o);
        int   oi = __shfl_xor_sync(0xffffffffu, i1, o);
        if (ov > v1 || (ov == v1 && oi < i1)) { v1 = ov; i1 = oi; }
    }
    float v2 = (lane < E_ && lane != i1) ? prob : -1.f; int i2 = lane;
    for (int o = 16; o; o >>= 1) {
        float ov = __shfl_xor_sync(0xffffffffu, v2, o);
        int   oi = __shfl_xor_sync(0xffffffffu, i2, o);
        if (ov > v2 || (ov == v2 && oi < i2)) { v2 = ov; i2 = oi; }
    }
    if (lane == 0) {
        float sw = v1 + v2;
        g_tw[b * 2 + 0] = v1 / sw;
        g_tw[b * 2 + 1] = v2 / sw;
        g_ti[b * 2 + 0] = i1;
        g_ti[b * 2 + 1] = i2;
    }
}

// ---------------------------------------------------------------------------
extern "C" void kernel_launch(void* const* d_in, const int* in_sizes, int n_in,
                              void* d_out, int out_size) {
    const float* x     = (const float*)d_in[0];
    const float* gamma = (const float*)d_in[1];
    const float* beta  = (const float*)d_in[2];
    const float* gw1   = (const float*)d_in[3];
    const float* gb1   = (const float*)d_in[4];
    const float* gw2   = (const float*)d_in[5];
    const float* gb2   = (const float*)d_in[6];
    const float* ew1   = (const float*)d_in[7];
    const float* eb1   = (const float*)d_in[8];
    const float* ew2   = (const float*)d_in[9];
    const float* eb2   = (const float*)d_in[10];
    float* out = (float*)d_out;

    float *pg;
    __nv_bfloat16 *phhi, *phlo, *pgw1hi, *pgw1lo;
    __half *phf, *pw1f, *pw2f, *phidf;
    cudaGetSymbolAddress((void**)&pg,     g_g);
    cudaGetSymbolAddress((void**)&phhi,   g_hhi);
    cudaGetSymbolAddress((void**)&phlo,   g_hlo);
    cudaGetSymbolAddress((void**)&pgw1hi, g_gw1hi);
    cudaGetSymbolAddress((void**)&pgw1lo, g_gw1lo);
    cudaGetSymbolAddress((void**)&phf,    g_hf);
    cudaGetSymbolAddress((void**)&pw1f,   g_w1f);
    cudaGetSymbolAddress((void**)&pw2f,   g_w2f);
    cudaGetSymbolAddress((void**)&phidf,  g_hidf);

    cudaFuncSetAttribute(gemm_f16<2>, cudaFuncAttributeMaxDynamicSharedMemorySize, SMEM_F);
    cudaFuncSetAttribute(gemm_f16<3>, cudaFuncAttributeMaxDynamicSharedMemorySize, SMEM_F);
    cudaFuncSetAttribute(gemm_gate,   cudaFuncAttributeMaxDynamicSharedMemorySize, SMEM_TC);

    // 1. LayerNorm: bf16 split (gating) + fp16 (experts)
    ln_kernel<<<B_, 256>>>(x, gamma, beta);

    // 2. ew1 transpose (fp16)
    transpose_f16_kernel<<<dim3(H_ / 32, D_ / 32, E_), dim3(32, 8)>>>(ew1, pw1f, D_, H_);

    // 3. Expert GEMM1 (fp16): hid[e] = gelu(h @ ew1[e] + eb1[e]), fp16 out
    gemm_f16<2><<<dim3(H_ / 128, B_ / 128, E_), 256, SMEM_F>>>(
        phf, pw1f, eb1,
        phidf, nullptr, nullptr,
        D_, 0, (size_t)H_ * D_, H_,
        (size_t)B_ * H_, H_, 0);

    // 4. Gating path (exact bf16x3): transpose, GEMM, softmax/top-2
    transpose_split_kernel<<<dim3(GH_ / 32, D_ / 32, 1), dim3(32, 8)>>>(gw1, pgw1hi, pgw1lo, D_, GH_);
    gemm_gate<<<dim3(GH_ / 128, B_ / 128, 1), 256, SMEM_TC>>>(
        phhi, phlo, pgw1hi, pgw1lo, gb1, pg, D_, GH_);
    gate_kernel<<<(B_ + 7) / 8, 256>>>(gw2, gb2, out);

    // 5. ew2 transpose (fp16) + zero result region
    transpose_f16_kernel<<<dim3(D_ / 32, H_ / 32, E_), dim3(32, 8)>>>(ew2, pw2f, H_, D_);
    zero_kernel<<<(int)(((size_t)B_ * D_ / 4 + 255) / 256), 256>>>(out, (size_t)B_ * D_ / 4);

    // 6. Expert GEMM2 (fp16) + fused top-k combine
    gemm_f16<3><<<dim3(D_ / 128, B_ / 128, E_), 256, SMEM_F>>>(
        phidf, pw2f, eb2,
        nullptr, out + OFF_EO, out,
        H_, (size_t)B_ * H_, (size_t)D_ * H_, D_,
        0, E_ * D_, D_);
}

// round 13
// speedup vs baseline: 7.7201x; 1.0827x over previous
#include <cuda_runtime.h>
#include <cuda_bf16.h>
#include <cuda_fp16.h>
#include <math.h>
#include <stdint.h>

#define B_  8192
#define D_  768
#define GH_ 384
#define E_  8
#define H_  3072

#define OFF_GATE ((size_t)B_ * D_)
#define OFF_EO   (OFF_GATE + (size_t)B_ * E_)

// Scratch
__device__ float g_g[(size_t)B_ * GH_];
__device__ __align__(16) __nv_bfloat16 g_hhi[(size_t)B_ * D_];   // gating path (exact)
__device__ __align__(16) __nv_bfloat16 g_hlo[(size_t)B_ * D_];
__device__ __align__(16) __nv_bfloat16 g_gw1hi[(size_t)GH_ * D_];
__device__ __align__(16) __nv_bfloat16 g_gw1lo[(size_t)GH_ * D_];
__device__ __align__(16) __half g_hf[(size_t)B_ * D_];           // fp16 expert path
__device__ __align__(16) __half g_w1f[(size_t)E_ * H_ * D_];
__device__ __align__(16) __half g_w2f[(size_t)E_ * D_ * H_];
__device__ __align__(16) __half g_hidf[(size_t)E_ * B_ * H_];
__device__ float g_tw[B_ * 2];
__device__ int   g_ti[B_ * 2];

__device__ __forceinline__ uint32_t smem_to_u32(const void* p) {
    uint32_t a;
    asm("{ .reg .u64 t; cvta.to.shared.u64 t, %1; cvt.u32.u64 %0, t; }" : "=r"(a) : "l"(p));
    return a;
}
// Fast exact-form gelu (A&S 7.1.26 erf, abs err 1.5e-7)
__device__ __forceinline__ float gelu_fast(float x) {
    float xs = x * 0.7071067811865476f;
    float ax = fabsf(xs);
    float t  = __fdividef(1.0f, fmaf(0.3275911f, ax, 1.0f));
    float y  = t * fmaf(t, fmaf(t, fmaf(t, fmaf(t, 1.061405429f, -1.453152027f),
                                        1.421413741f), -0.284496736f), 0.254829592f);
    float ev = 1.0f - y * __expf(-ax * ax);
    ev = copysignf(ev, xs);
    return 0.5f * x * (1.0f + ev);
}
__device__ __forceinline__ void splitbf(float v, __nv_bfloat16& h, __nv_bfloat16& l) {
    h = __float2bfloat16(v);
    l = __float2bfloat16(v - __bfloat162float(h));
}
__device__ __forceinline__ uint32_t packh2(float v0, float v1) {
    uint32_t p;
    asm("cvt.rn.f16x2.f32 %0, %1, %2;" : "=r"(p) : "f"(v1), "f"(v0));
    return p;  // lo half = v0
}
__device__ __forceinline__ void cpa16(uint32_t dst, const void* src) {
    asm volatile("cp.async.cg.shared.global [%0], [%1], 16;" :: "r"(dst), "l"(src));
}
#define CP_COMMIT() asm volatile("cp.async.commit_group;" ::: "memory")
#define CP_WAIT1()  asm volatile("cp.async.wait_group 1;" ::: "memory")
#define CP_WAIT0()  asm volatile("cp.async.wait_group 0;" ::: "memory")

#define LDSM4(r, addr)                                                          \
    asm volatile("ldmatrix.sync.aligned.m8n8.x4.shared.b16 {%0,%1,%2,%3}, [%4];"\
                 : "=r"((r)[0]), "=r"((r)[1]), "=r"((r)[2]), "=r"((r)[3])       \
                 : "r"(addr))

#define MMA_BF16(d, a, b0, b1)                                                  \
    asm volatile("mma.sync.aligned.m16n8k16.row.col.f32.bf16.bf16.f32 "         \
                 "{%0,%1,%2,%3}, {%4,%5,%6,%7}, {%8,%9}, {%0,%1,%2,%3};"        \
                 : "+f"((d)[0]), "+f"((d)[1]), "+f"((d)[2]), "+f"((d)[3])       \
                 : "r"((a)[0]), "r"((a)[1]), "r"((a)[2]), "r"((a)[3]),          \
                   "r"(b0), "r"(b1))

#define MMA_F16(d, a, b0, b1)                                                   \
    asm volatile("mma.sync.aligned.m16n8k16.row.col.f32.f16.f16.f32 "           \
                 "{%0,%1,%2,%3}, {%4,%5,%6,%7}, {%8,%9}, {%0,%1,%2,%3};"        \
                 : "+f"((d)[0]), "+f"((d)[1]), "+f"((d)[2]), "+f"((d)[3])       \
                 : "r"((a)[0]), "r"((a)[1]), "r"((a)[2]), "r"((a)[3]),          \
                   "r"(b0), "r"(b1))

// ---------------------------------------------------------------------------
// LayerNorm: bf16 hi/lo (gating) + fp16 single plane (experts)
// ---------------------------------------------------------------------------
__global__ void ln_kernel(const float* __restrict__ x,
                          const float* __restrict__ gamma,
                          const float* __restrict__ beta) {
    int b = blockIdx.x;
    const float* row = x + (size_t)b * D_;
    float s = 0.f, s2 = 0.f;
    for (int i = threadIdx.x; i < D_; i += blockDim.x) {
        float v = row[i];
        s += v; s2 += v * v;
    }
    __shared__ float red[64];
    for (int o = 16; o; o >>= 1) {
        s  += __shfl_down_sync(0xffffffffu, s,  o);
        s2 += __shfl_down_sync(0xffffffffu, s2, o);
    }
    int wid = threadIdx.x >> 5, lid = threadIdx.x & 31;
    if (lid == 0) { red[wid] = s; red[wid + 32] = s2; }
    __syncthreads();
    int nw = blockDim.x >> 5;
    if (wid == 0) {
        s  = (lid < nw) ? red[lid]      : 0.f;
        s2 = (lid < nw) ? red[lid + 32] : 0.f;
        for (int o = 16; o; o >>= 1) {
            s  += __shfl_down_sync(0xffffffffu, s,  o);
            s2 += __shfl_down_sync(0xffffffffu, s2, o);
        }
        if (lid == 0) { red[0] = s; red[1] = s2; }
    }
    __syncthreads();
    float mu   = red[0] / D_;
    float var  = red[1] / D_ - mu * mu;
    float rstd = rsqrtf(var + 1e-5f);
    for (int i = threadIdx.x; i < D_; i += blockDim.x) {
        float v = (row[i] - mu) * rstd * gamma[i] + beta[i];
        size_t idx = (size_t)b * D_ + i;
        __nv_bfloat16 hi, lo;
        splitbf(v, hi, lo);
        g_hhi[idx] = hi;
        g_hlo[idx] = lo;
        g_hf[idx]  = __float2half_rn(v);
    }
}

// ---------------------------------------------------------------------------
// Transposes: fp16 single-plane (expert weights) and bf16 split (gating)
// ---------------------------------------------------------------------------
__global__ void transpose_f16_kernel(const float* __restrict__ src,
                                     __half* __restrict__ dst, int R, int C) {
    __shared__ float t[32][33];
    int e = blockIdx.z;
    int c0 = blockIdx.x * 32, r0 = blockIdx.y * 32;
    const float* s = src + (size_t)e * R * C;
    #pragma unroll
    for (int i = 0; i < 32; i += 8)
        t[threadIdx.y + i][threadIdx.x] =
            s[(size_t)(r0 + threadIdx.y + i) * C + c0 + threadIdx.x];
    __syncthreads();
    size_t ob = (size_t)e * C * R;
    #pragma unroll
    for (int i = 0; i < 32; i += 8)
        dst[ob + (size_t)(c0 + threadIdx.y + i) * R + r0 + threadIdx.x] =
            __float2half_rn(t[threadIdx.x][threadIdx.y + i]);
}

__global__ void transpose_split_kernel(const float* __restrict__ src,
                                       __nv_bfloat16* __restrict__ dhi,
                                       __nv_bfloat16* __restrict__ dlo,
                                       int R, int C) {
    __shared__ float t[32][33];
    int c0 = blockIdx.x * 32, r0 = blockIdx.y * 32;
    #pragma unroll
    for (int i = 0; i < 32; i += 8)
        t[threadIdx.y + i][threadIdx.x] =
            src[(size_t)(r0 + threadIdx.y + i) * C + c0 + threadIdx.x];
    __syncthreads();
    #pragma unroll
    for (int i = 0; i < 32; i += 8) {
        float v = t[threadIdx.x][threadIdx.y + i];
        __nv_bfloat16 hi, lo;
        splitbf(v, hi, lo);
        size_t o = (size_t)(c0 + threadIdx.y + i) * R + r0 + threadIdx.x;
        dhi[o] = hi;
        dlo[o] = lo;
    }
}

__global__ void zero_kernel(float* __restrict__ p, size_t n4) {
    size_t i = (size_t)blockIdx.x * blockDim.x + threadIdx.x;
    if (i < n4) ((float4*)p)[i] = make_float4(0.f, 0.f, 0.f, 0.f);
}

// ---------------------------------------------------------------------------
// fp16 single-plane GEMM: 128x128x64 CTA chunks, 8 warps 64x32, 256 thr,
// 128B-pitch SW128-swizzled smem (seg ^= row&7), 3-stage pipeline, 2 CTAs/SM.
// 64 MMAs per sync point (vs 16 at BK=32) -> halved barrier overhead.
// OUT_MODE: 2 = gelu + fp16 out (GEMM1), 3 = fp32 +bias + fused combine (GEMM2)
// ---------------------------------------------------------------------------
#define FPLANE 16384                     // 128 rows * 128B
#define FSTAGE (2 * FPLANE)              // A|B = 32768
#define FNSTG 3
#define SMEM_F (FNSTG * FSTAGE)          // 98304

template <int OUT_MODE>
__global__ void __launch_bounds__(256, 2) gemm_f16(
    const __half* __restrict__ Ah, const __half* __restrict__ Bh,
    const float* __restrict__ bias,
    __half* __restrict__ OutH, float* __restrict__ OutF, float* __restrict__ Res,
    int Ktot, size_t aStrideE, size_t bStrideE, size_t biasStrideE,
    size_t cStrideE, int ldc, int cColStride)
{
    extern __shared__ char smem[];
    uint32_t sbase = smem_to_u32(smem);
    int tid  = threadIdx.x;
    int warp = tid >> 5, lane = tid & 31;
    int e  = blockIdx.z;
    int bm = blockIdx.y * 128;
    int bn = blockIdx.x * 128;
    int wm = (warp >> 2) * 64;
    int wn = (warp & 3)  * 32;
    int g  = lane >> 2, tg = lane & 3;
    int mi = lane >> 3, rr = lane & 7;

    const __half* pA = Ah + (size_t)e * aStrideE + (size_t)bm * Ktot;
    const __half* pB = Bh + (size_t)e * bStrideE + (size_t)bn * Ktot;

    // ldmatrix lane addressing (128B pitch, seg ^= row&7 on 16B segments)
    int arow = wm + (mi & 1) * 8 + rr;
    uint32_t aoff = (uint32_t)arow * 128;
    int aswz = arow & 7;
    int akseg = mi >> 1;                 // 16B half within each k16 step
    int brow = wn + (mi >> 1) * 8 + rr;
    uint32_t boff = (uint32_t)brow * 128;
    int bswz = brow & 7;
    int bkseg = mi & 1;

    float acc[4][4][4];
    #pragma unroll
    for (int i = 0; i < 4; i++)
        #pragma unroll
        for (int j = 0; j < 4; j++)
            #pragma unroll
            for (int r = 0; r < 4; r++) acc[i][j][r] = 0.f;

    const int NC = Ktot / 64;

    auto load_chunk = [&](int c, int st) {
        int k0 = c * 64;
        uint32_t sb = sbase + (uint32_t)st * FSTAGE;
        #pragma unroll
        for (int i = 0; i < 4; i++) {            // 1024 16B units per plane
            int p = tid + i * 256;
            int row = p >> 3, seg = p & 7;
            uint32_t d = sb + (uint32_t)row * 128
                       + (uint32_t)((seg ^ (row & 7)) << 4);
            size_t go = (size_t)row * Ktot + k0 + seg * 8;
            cpa16(d,          pA + go);
            cpa16(d + FPLANE, pB + go);
        }
        CP_COMMIT();
    };

    load_chunk(0, 0);
    if (NC > 1) load_chunk(1, 1);

    for (int c = 0; c < NC; c++) {
        if (c + 1 < NC) { CP_WAIT1(); } else { CP_WAIT0(); }
        __syncthreads();
        // Stage (c+2)%3 consumed in iter c-1 (ordered by sync above): refill now.
        if (c + 2 < NC) load_chunk(c + 2, (c + 2) % FNSTG);

        uint32_t sb = sbase + (uint32_t)((c % FNSTG) * FSTAGE);
        #pragma unroll
        for (int ks = 0; ks < 4; ks++) {         // 4 k16 steps per chunk
            uint32_t af[4][4], bf[2][4];
            #pragma unroll
            for (int i = 0; i < 4; i++) {
                uint32_t ad = sb + aoff + (uint32_t)i * 2048
                            + (uint32_t)(((ks * 2 + akseg) ^ aswz) << 4);
                LDSM4(af[i], ad);
            }
            #pragma unroll
            for (int jp = 0; jp < 2; jp++) {
                uint32_t bd = sb + FPLANE + boff + (uint32_t)jp * 2048
                            + (uint32_t)(((ks * 2 + bkseg) ^ bswz) << 4);
                LDSM4(bf[jp], bd);
            }
            #pragma unroll
            for (int i = 0; i < 4; i++)
                #pragma unroll
                for (int j = 0; j < 4; j++) {
                    int jp = j >> 1, hf = (j & 1) * 2;
                    MMA_F16(acc[i][j], af[i], bf[jp][hf], bf[jp][hf + 1]);
                }
        }
    }

    const float* bp = bias + (size_t)e * biasStrideE;
    #pragma unroll
    for (int i = 0; i < 4; i++) {
        int r0 = bm + wm + i * 16 + g;
        float cw0 = 0.f, cw1 = 0.f;
        if (OUT_MODE == 3) {
            int i00 = g_ti[r0 * 2], i01 = g_ti[r0 * 2 + 1];
            cw0 = (i00 == e) ? g_tw[r0 * 2] : ((i01 == e) ? g_tw[r0 * 2 + 1] : 0.f);
            int r1 = r0 + 8;
            int i10 = g_ti[r1 * 2], i11 = g_ti[r1 * 2 + 1];
            cw1 = (i10 == e) ? g_tw[r1 * 2] : ((i11 == e) ? g_tw[r1 * 2 + 1] : 0.f);
        }
        #pragma unroll
        for (int j = 0; j < 4; j++) {
            int c0 = bn + wn + j * 8 + tg * 2;
            float bi0 = bp[c0], bi1 = bp[c0 + 1];
            float v0 = acc[i][j][0] + bi0, v1 = acc[i][j][1] + bi1;
            float v2 = acc[i][j][2] + bi0, v3 = acc[i][j][3] + bi1;
            size_t rbA = (size_t)e * cStrideE + (size_t)r0 * ldc
                       + (size_t)e * cColStride + c0;
            size_t rbB = rbA + (size_t)8 * ldc;
            if (OUT_MODE == 3) {
                OutF[rbA] = v0; OutF[rbA + 1] = v1;
                OutF[rbB] = v2; OutF[rbB + 1] = v3;
                if (cw0 != 0.f) {
                    atomicAdd(&Res[(size_t)r0 * D_ + c0],     cw0 * v0);
                    atomicAdd(&Res[(size_t)r0 * D_ + c0 + 1], cw0 * v1);
                }
                if (cw1 != 0.f) {
                    atomicAdd(&Res[(size_t)(r0 + 8) * D_ + c0],     cw1 * v2);
                    atomicAdd(&Res[(size_t)(r0 + 8) * D_ + c0 + 1], cw1 * v3);
                }
            } else {  // OUT_MODE 2: gelu + fp16
                v0 = gelu_fast(v0); v1 = gelu_fast(v1);
                v2 = gelu_fast(v2); v3 = gelu_fast(v3);
                *(uint32_t*)(OutH + rbA) = packh2(v0, v1);
                *(uint32_t*)(OutH + rbB) = packh2(v2, v3);
            }
        }
    }
}

// ---------------------------------------------------------------------------
// Exact bf16x3 gating GEMM (unchanged, gelu fp32 out)
// ---------------------------------------------------------------------------
#define PLANE_B 8192
#define STAGE_B (4 * PLANE_B)
#define NSTG 3
#define SMEM_TC (NSTG * STAGE_B)

__global__ void __launch_bounds__(256, 2) gemm_gate(
    const __nv_bfloat16* __restrict__ Ahi, const __nv_bfloat16* __restrict__ Alo,
    const __nv_bfloat16* __restrict__ Bhi, const __nv_bfloat16* __restrict__ Blo,
    const float* __restrict__ bias, float* __restrict__ OutF,
    int Ktot, int ldc)
{
    extern __shared__ char smem[];
    uint32_t sbase = smem_to_u32(smem);
    int tid  = threadIdx.x;
    int warp = tid >> 5, lane = tid & 31;
    int bm = blockIdx.y * 128;
    int bn = blockIdx.x * 128;
    int wm = (warp >> 2) * 64;
    int wn = (warp & 3)  * 32;
    int g  = lane >> 2, tg = lane & 3;
    int mi = lane >> 3, rr = lane & 7;

    const __nv_bfloat16* pAhi = Ahi + (size_t)bm * Ktot;
    const __nv_bfloat16* pAlo = Alo + (size_t)bm * Ktot;
    const __nv_bfloat16* pBhi = Bhi + (size_t)bn * Ktot;
    const __nv_bfloat16* pBlo = Blo + (size_t)bn * Ktot;

    int arow = wm + (mi & 1) * 8 + rr;
    uint32_t aoff = (uint32_t)arow * 64;
    uint32_t aswz = (uint32_t)(((arow >> 1) & 3) << 4);
    int akseg = mi >> 1;
    int brow = wn + (mi >> 1) * 8 + rr;
    uint32_t boff = (uint32_t)brow * 64;
    uint32_t bswz = (uint32_t)(((brow >> 1) & 3) << 4);
    int bkseg = mi & 1;

    float acc[4][4][4];
    #pragma unroll
    for (int i = 0; i < 4; i++)
        #pragma unroll
        for (int j = 0; j < 4; j++)
            #pragma unroll
            for (int r = 0; r < 4; r++) acc[i][j][r] = 0.f;

    const int NC = Ktot / 32;

    auto load_chunk = [&](int c, int st) {
        int k0 = c * 32;
        uint32_t sb = sbase + (uint32_t)st * STAGE_B;
        #pragma unroll
        for (int i = 0; i < 2; i++) {
            int p = tid + i * 256;
            int row = p >> 2, col = p & 3;
            uint32_t d = sb + (uint32_t)row * 64
                       + (uint32_t)((col ^ ((row >> 1) & 3)) << 4);
            size_t go = (size_t)row * Ktot + k0 + col * 8;
            cpa16(d,                 pAhi + go);
            cpa16(d + PLANE_B,       pAlo + go);
            cpa16(d + 2u * PLANE_B,  pBhi + go);
            cpa16(d + 3u * PLANE_B,  pBlo + go);
        }
        CP_COMMIT();
    };

    load_chunk(0, 0);
    if (NC > 1) load_chunk(1, 1);

    for (int c = 0; c < NC; c++) {
        if (c + 1 < NC) { CP_WAIT1(); } else { CP_WAIT0(); }
        __syncthreads();
        if (c + 2 < NC) load_chunk(c + 2, (c + 2) % NSTG);

        uint32_t sb = sbase + (uint32_t)((c % NSTG) * STAGE_B);
        #pragma unroll
        for (int ks = 0; ks < 2; ks++) {
            uint32_t ah[4][4], al[4][4], bh[2][4], bl[2][4];
            #pragma unroll
            for (int i = 0; i < 4; i++) {
                uint32_t ad = sb + aoff + (uint32_t)i * 1024
                            + (((uint32_t)(ks * 2 + akseg) << 4) ^ aswz);
                LDSM4(ah[i], ad);
                LDSM4(al[i], ad + PLANE_B);
            }
            #pragma unroll
            for (int jp = 0; jp < 2; jp++) {
                uint32_t bd = sb + 2u * PLANE_B + boff + (uint32_t)jp * 1024
                            + (((uint32_t)(ks * 2 + bkseg) << 4) ^ bswz);
                LDSM4(bh[jp], bd);
                LDSM4(bl[jp], bd + PLANE_B);
            }
            #pragma unroll
            for (int i = 0; i < 4; i++)
                #pragma unroll
                for (int j = 0; j < 4; j++) {
                    int jp = j >> 1, hf = (j & 1) * 2;
                    MMA_BF16(acc[i][j], ah[i], bh[jp][hf], bh[jp][hf + 1]);
                }
            #pragma unroll
            for (int i = 0; i < 4; i++)
                #pragma unroll
                for (int j = 0; j < 4; j++) {
                    int jp = j >> 1, hf = (j & 1) * 2;
                    MMA_BF16(acc[i][j], ah[i], bl[jp][hf], bl[jp][hf + 1]);
                }
            #pragma unroll
            for (int i = 0; i < 4; i++)
                #pragma unroll
                for (int j = 0; j < 4; j++) {
                    int jp = j >> 1, hf = (j & 1) * 2;
                    MMA_BF16(acc[i][j], al[i], bh[jp][hf], bh[jp][hf + 1]);
                }
        }
    }

    #pragma unroll
    for (int i = 0; i < 4; i++) {
        int r0 = bm + wm + i * 16 + g;
        #pragma unroll
        for (int j = 0; j < 4; j++) {
            int c0 = bn + wn + j * 8 + tg * 2;
            float bi0 = bias[c0], bi1 = bias[c0 + 1];
            size_t rbA = (size_t)r0 * ldc + c0;
            size_t rbB = rbA + (size_t)8 * ldc;
            OutF[rbA]     = gelu_fast(acc[i][j][0] + bi0);
            OutF[rbA + 1] = gelu_fast(acc[i][j][1] + bi1);
            OutF[rbB]     = gelu_fast(acc[i][j][2] + bi0);
            OutF[rbB + 1] = gelu_fast(acc[i][j][3] + bi1);
        }
    }
}

// ---------------------------------------------------------------------------
__global__ void gate_kernel(const float* __restrict__ gw2,
                            const float* __restrict__ gb2,
                            float* __restrict__ dout) {
    int b = blockIdx.x * (blockDim.x >> 5) + (threadIdx.x >> 5);
    if (b >= B_) return;
    int lane = threadIdx.x & 31;
    int e = lane & 7, s = lane >> 3;

    const float* gr = g_g + (size_t)b * GH_;
    float acc = 0.f;
    int k0 = s * (GH_ / 4);
    #pragma unroll 4
    for (int k = k0; k < k0 + GH_ / 4; k++)
        acc = fmaf(gr[k], gw2[k * E_ + e], acc);
    acc += __shfl_xor_sync(0xffffffffu, acc, 8);
    acc += __shfl_xor_sync(0xffffffffu, acc, 16);
    float logit = acc + gb2[e];

    float m = logit;
    for (int o = 4; o; o >>= 1) m = fmaxf(m, __shfl_xor_sync(0xffffffffu, m, o));
    float p = (lane < E_) ? expf(logit - m) : 0.f;
    float ssum = p;
    for (int o = 16; o; o >>= 1) ssum += __shfl_xor_sync(0xffffffffu, ssum, o);
    float prob = p / ssum;
    if (lane < E_) dout[OFF_GATE + (size_t)b * E_ + lane] = prob;

    float v1 = (lane < E_) ? prob : -1.f; int i1 = lane;
    for (int o = 16; o; o >>= 1) {
        float ov = __shfl_xor_sync(0xffffffffu, v1, o);
        int   oi = __shfl_xor_sync(0xffffffffu, i1, o);
        if (ov > v1 || (ov == v1 && oi < i1)) { v1 = ov; i1 = oi; }
    }
    float v2 = (lane < E_ && lane != i1) ? prob : -1.f; int i2 = lane;
    for (int o = 16; o; o >>= 1) {
        float ov = __shfl_xor_sync(0xffffffffu, v2, o);
        int   oi = __shfl_xor_sync(0xffffffffu, i2, o);
        if (ov > v2 || (ov == v2 && oi < i2)) { v2 = ov; i2 = oi; }
    }
    if (lane == 0) {
        float sw = v1 + v2;
        g_tw[b * 2 + 0] = v1 / sw;
        g_tw[b * 2 + 1] = v2 / sw;
        g_ti[b * 2 + 0] = i1;
        g_ti[b * 2 + 1] = i2;
    }
}

// ---------------------------------------------------------------------------
extern "C" void kernel_launch(void* const* d_in, const int* in_sizes, int n_in,
                              void* d_out, int out_size) {
    const float* x     = (const float*)d_in[0];
    const float* gamma = (const float*)d_in[1];
    const float* beta  = (const float*)d_in[2];
    const float* gw1   = (const float*)d_in[3];
    const float* gb1   = (const float*)d_in[4];
    const float* gw2   = (const float*)d_in[5];
    const float* gb2   = (const float*)d_in[6];
    const float* ew1   = (const float*)d_in[7];
    const float* eb1   = (const float*)d_in[8];
    const float* ew2   = (const float*)d_in[9];
    const float* eb2   = (const float*)d_in[10];
    float* out = (float*)d_out;

    float *pg;
    __nv_bfloat16 *phhi, *phlo, *pgw1hi, *pgw1lo;
    __half *phf, *pw1f, *pw2f, *phidf;
    cudaGetSymbolAddress((void**)&pg,     g_g);
    cudaGetSymbolAddress((void**)&phhi,   g_hhi);
    cudaGetSymbolAddress((void**)&phlo,   g_hlo);
    cudaGetSymbolAddress((void**)&pgw1hi, g_gw1hi);
    cudaGetSymbolAddress((void**)&pgw1lo, g_gw1lo);
    cudaGetSymbolAddress((void**)&phf,    g_hf);
    cudaGetSymbolAddress((void**)&pw1f,   g_w1f);
    cudaGetSymbolAddress((void**)&pw2f,   g_w2f);
    cudaGetSymbolAddress((void**)&phidf,  g_hidf);

    cudaFuncSetAttribute(gemm_f16<2>, cudaFuncAttributeMaxDynamicSharedMemorySize, SMEM_F);
    cudaFuncSetAttribute(gemm_f16<3>, cudaFuncAttributeMaxDynamicSharedMemorySize, SMEM_F);
    cudaFuncSetAttribute(gemm_gate,   cudaFuncAttributeMaxDynamicSharedMemorySize, SMEM_TC);

    // 1. LayerNorm: bf16 split (gating) + fp16 (experts)
    ln_kernel<<<B_, 256>>>(x, gamma, beta);

    // 2. ew1 transpose (fp16)
    transpose_f16_kernel<<<dim3(H_ / 32, D_ / 32, E_), dim3(32, 8)>>>(ew1, pw1f, D_, H_);

    // 3. Expert GEMM1 (fp16): hid[e] = gelu(h @ ew1[e] + eb1[e]), fp16 out
    gemm_f16<2><<<dim3(H_ / 128, B_ / 128, E_), 256, SMEM_F>>>(
        phf, pw1f, eb1,
        phidf, nullptr, nullptr,
        D_, 0, (size_t)H_ * D_, H_,
        (size_t)B_ * H_, H_, 0);

    // 4. Gating path (exact bf16x3): transpose, GEMM, softmax/top-2
    transpose_split_kernel<<<dim3(GH_ / 32, D_ / 32, 1), dim3(32, 8)>>>(gw1, pgw1hi, pgw1lo, D_, GH_);
    gemm_gate<<<dim3(GH_ / 128, B_ / 128, 1), 256, SMEM_TC>>>(
        phhi, phlo, pgw1hi, pgw1lo, gb1, pg, D_, GH_);
    gate_kernel<<<(B_ + 7) / 8, 256>>>(gw2, gb2, out);

    // 5. ew2 transpose (fp16) + zero result region
    transpose_f16_kernel<<<dim3(D_ / 32, H_ / 32, E_), dim3(32, 8)>>>(ew2, pw2f, H_, D_);
    zero_kernel<<<(int)(((size_t)B_ * D_ / 4 + 255) / 256), 256>>>(out, (size_t)B_ * D_ / 4);

    // 6. Expert GEMM2 (fp16) + fused top-k combine
    gemm_f16<3><<<dim3(D_ / 128, B_ / 128, E_), 256, SMEM_F>>>(
        phidf, pw2f, eb2,
        nullptr, out + OFF_EO, out,
        H_, (size_t)B_ * H_, (size_t)D_ * H_, D_,
        0, E_ * D_, D_);
}